// round 7
// baseline (speedup 1.0000x reference)
#include <cuda_runtime.h>
#include <cuda_bf16.h>
#include <cstdint>

#define EMB    512
#define HID    512
#define NCLASS 50257
#define BATCH  64
#define STEPS  256
#define FOURH  2048

// ---------------- scratch (device globals; no mallocs allowed) ---------------
__device__ float    g_xw[STEPS * BATCH * FOURH];   // 128 MiB precomputed input proj
__device__ float    g_h[2 * BATCH * HID];          // double-buffered hidden state
__device__ float    g_bsum[FOURH];                 // bi + bh
// barrier words on SEPARATE 128B L2 lines
__device__ __align__(128) unsigned g_barc[32];     // monotonic arrival counter
__device__ __align__(128) unsigned g_barp[32];     // monotonic phase

// ---------------- packed f32x2 helpers (sm_103a) ------------------------------
__device__ __forceinline__ unsigned long long pack2(float x, float y) {
    unsigned long long r;
    asm("mov.b64 %0, {%1, %2};" : "=l"(r) : "f"(x), "f"(y));
    return r;
}
__device__ __forceinline__ void fma2(unsigned long long& acc,
                                     unsigned long long a, unsigned long long b) {
    asm("fma.rn.f32x2 %0, %1, %2, %0;" : "+l"(acc) : "l"(a), "l"(b));
}
__device__ __forceinline__ float2 unpack2(unsigned long long v) {
    float2 f;
    asm("mov.b64 {%0, %1}, %2;" : "=f"(f.x), "=f"(f.y) : "l"(v));
    return f;
}
__device__ __forceinline__ float hsum2(unsigned long long v) {
    float2 f = unpack2(v);
    return f.x + f.y;
}
__device__ __forceinline__ unsigned long long f4lo(const float4& v) {
    return ((const unsigned long long*)&v)[0];
}
__device__ __forceinline__ unsigned long long f4hi(const float4& v) {
    return ((const unsigned long long*)&v)[1];
}
__device__ __forceinline__ float fsigmoid_(float x) {
    return __fdividef(1.0f, 1.0f + __expf(-x));
}
__device__ __forceinline__ float ftanh_(float x) {
    return 2.0f * __fdividef(1.0f, 1.0f + __expf(-2.0f * x)) - 1.0f;
}
// cp.async 16B, L2-only (.cg) — coherent across the grid barrier, no L1 staleness
__device__ __forceinline__ void cpasync16(unsigned dst, const void* src) {
    asm volatile("cp.async.cg.shared.global [%0], [%1], 16;"
                 :: "r"(dst), "l"(src) : "memory");
}
template <int N>
__device__ __forceinline__ void cpasync_wait() {
    asm volatile("cp.async.wait_group %0;" :: "n"(N) : "memory");
}

// ---------------- flat grid barrier (monotonic, release/acquire) --------------
__device__ __forceinline__ void grid_barrier(unsigned nct, unsigned target) {
    __syncthreads();
    if (threadIdx.x == 0) {
        unsigned old;
        asm volatile("atom.release.gpu.global.add.u32 %0, [%1], 1;"
                     : "=r"(old) : "l"(&g_barc[0]) : "memory");
        if (old + 1u == target * nct) {
            asm volatile("st.release.gpu.global.u32 [%0], %1;"
                         :: "l"(&g_barp[0]), "r"(target) : "memory");
        } else {
            unsigned cur;
            do {
                asm volatile("ld.acquire.gpu.global.u32 %0, [%1];"
                             : "=r"(cur) : "l"(&g_barp[0]) : "memory");
            } while (cur < target);
        }
    }
    __syncthreads();
}

// ---------------- kernel 0: prep (bsum = bi + bh, zero h, reset barrier) ------
__global__ void prep_kernel(const float* __restrict__ bi, const float* __restrict__ bh) {
    int i = blockIdx.x * blockDim.x + threadIdx.x;
    int stride = gridDim.x * blockDim.x;
    if (i < 32) { g_barc[i] = 0u; g_barp[i] = 0u; }
    if (i < FOURH) g_bsum[i] = bi[i] + bh[i];
    for (int j = i; j < 2 * BATCH * HID; j += stride) g_h[j] = 0.0f;
}

// ---------------- kernel 1: xw = gather(emb, X) @ Wi + bsum -------------------
__global__ __launch_bounds__(256, 2) void xw_gemm_kernel(
    const int* __restrict__ X, const float* __restrict__ emb,
    const float* __restrict__ Wi) {
    __shared__ float As[2][16][132];
    __shared__ float Bs[2][16][132];
    __shared__ int   tok[128];

    const int tid = threadIdx.x;
    const int m0 = blockIdx.y * 128;
    const int n0 = blockIdx.x * 128;
    const int tm = tid >> 4, tn = tid & 15;

    const int arow0 = tid >> 2,            ac4_0 = tid & 3;
    const int arow1 = (tid + 256) >> 2,    ac4_1 = (tid + 256) & 3;
    const int bk0   = tid >> 5,            bc4_0 = tid & 31;
    const int bk1   = (tid + 256) >> 5,    bc4_1 = (tid + 256) & 31;

    if (tid < 128) {
        int m = m0 + tid;
        int b = m & 63, t = m >> 6;
        tok[tid] = X[b * STEPS + t];
    }
    __syncthreads();

    unsigned long long acc[8][4];
#pragma unroll
    for (int i = 0; i < 8; ++i)
#pragma unroll
        for (int j = 0; j < 4; ++j) acc[i][j] = 0ull;

    float4 pa0 = *(const float4*)(emb + (size_t)tok[arow0] * EMB + ac4_0 * 4);
    float4 pa1 = *(const float4*)(emb + (size_t)tok[arow1] * EMB + ac4_1 * 4);
    float4 pb0 = *(const float4*)(Wi + (size_t)bk0 * FOURH + n0 + bc4_0 * 4);
    float4 pb1 = *(const float4*)(Wi + (size_t)bk1 * FOURH + n0 + bc4_1 * 4);

    int cur = 0;
    for (int kt = 0; kt < EMB; kt += 16) {
        As[cur][ac4_0 * 4 + 0][arow0] = pa0.x;
        As[cur][ac4_0 * 4 + 1][arow0] = pa0.y;
        As[cur][ac4_0 * 4 + 2][arow0] = pa0.z;
        As[cur][ac4_0 * 4 + 3][arow0] = pa0.w;
        As[cur][ac4_1 * 4 + 0][arow1] = pa1.x;
        As[cur][ac4_1 * 4 + 1][arow1] = pa1.y;
        As[cur][ac4_1 * 4 + 2][arow1] = pa1.z;
        As[cur][ac4_1 * 4 + 3][arow1] = pa1.w;
        *(float4*)&Bs[cur][bk0][bc4_0 * 4] = pb0;
        *(float4*)&Bs[cur][bk1][bc4_1 * 4] = pb1;
        if (kt + 16 < EMB) {
            int kn = kt + 16;
            pa0 = *(const float4*)(emb + (size_t)tok[arow0] * EMB + kn + ac4_0 * 4);
            pa1 = *(const float4*)(emb + (size_t)tok[arow1] * EMB + kn + ac4_1 * 4);
            pb0 = *(const float4*)(Wi + (size_t)(kn + bk0) * FOURH + n0 + bc4_0 * 4);
            pb1 = *(const float4*)(Wi + (size_t)(kn + bk1) * FOURH + n0 + bc4_1 * 4);
        }
        __syncthreads();
#pragma unroll
        for (int kk = 0; kk < 16; ++kk) {
            float4 a0 = *(const float4*)&As[cur][kk][tm * 8];
            float4 a1 = *(const float4*)&As[cur][kk][tm * 8 + 4];
            float4 b0 = *(const float4*)&Bs[cur][kk][tn * 8];
            float4 b1 = *(const float4*)&Bs[cur][kk][tn * 8 + 4];
            unsigned long long bp0 = f4lo(b0), bp1 = f4hi(b0);
            unsigned long long bp2 = f4lo(b1), bp3 = f4hi(b1);
            float av[8] = {a0.x, a0.y, a0.z, a0.w, a1.x, a1.y, a1.z, a1.w};
#pragma unroll
            for (int i = 0; i < 8; ++i) {
                unsigned long long ad = pack2(av[i], av[i]);
                fma2(acc[i][0], ad, bp0);
                fma2(acc[i][1], ad, bp1);
                fma2(acc[i][2], ad, bp2);
                fma2(acc[i][3], ad, bp3);
            }
        }
        cur ^= 1;
    }

    const float4 bs0 = *(const float4*)&g_bsum[n0 + tn * 8];
    const float4 bs1 = *(const float4*)&g_bsum[n0 + tn * 8 + 4];
    const float bsv[8] = {bs0.x, bs0.y, bs0.z, bs0.w, bs1.x, bs1.y, bs1.z, bs1.w};
#pragma unroll
    for (int i = 0; i < 8; ++i) {
        int m = m0 + tm * 8 + i;
        float o[8];
#pragma unroll
        for (int j = 0; j < 4; ++j) {
            float2 v = unpack2(acc[i][j]);
            o[2 * j] = v.x + bsv[2 * j];
            o[2 * j + 1] = v.y + bsv[2 * j + 1];
        }
        float* orow = g_xw + (size_t)m * FOURH + n0 + tn * 8;
        *(float4*)&orow[0] = make_float4(o[0], o[1], o[2], o[3]);
        *(float4*)&orow[4] = make_float4(o[4], o[5], o[6], o[7]);
    }
}

// ---------------- kernel 2: persistent LSTM, pipelined staging ----------------
// 128 CTAs x 256 thr. CTA owns 16 gate-cols. Lane = (col 0..15, k-quad 0..1);
// warp owns 8 batches. W stationary per lane; h via LDS broadcast.
// h staged in 4 k-chunks (cp.async.cg groups) overlapped with the GEMM.
__global__ __launch_bounds__(256, 1) void lstm_kernel(const float* __restrict__ Wh) {
    extern __shared__ __align__(16) float sm[];
    float* w_s  = sm;                    // 8192 floats (32 KB)
    float* h_s  = sm + 8192;             // 32768 floats (128 KB)
    float* spre = sm + 8192 + 32768;     // 16*65 floats

    const int tid = threadIdx.x;
    const int cta = blockIdx.x;
    const unsigned nct = gridDim.x;
    const int lane = tid & 31, wrp = tid >> 5;

    // one-time: rearrange this CTA's 16 Wh columns into per-lane layout
    for (int i = tid; i < 8192; i += 256) {
        int j  = i & 3;
        int ln = (i >> 2) & 31;
        int it = i >> 7;
        int c  = ln & 15;
        int k  = it * 8 + (ln >> 4) * 4 + j;
        int gcol = (c >> 2) * HID + cta * 4 + (c & 3);
        w_s[i] = Wh[(size_t)k * FOURH + gcol];
    }

    const int col = lane & 15, kq = lane >> 4;
    const int ub = tid >> 2, uu = tid & 3;     // update mapping: batch, unit
    float creg = 0.0f;                          // cell state lives in a register

    const unsigned hs_u32 = (unsigned)__cvta_generic_to_shared(h_s);
    const float* hrow = h_s + wrp * 8 * HID + kq * 4;
    const float* wp   = w_s + lane * 4;

    // chunk loader mapping: per chunk 2048 float4; 8 per thread
    const int sb   = tid >> 2;           // staging batch row 0..63 (4 thr/row)
    const int soff = (tid & 3) * 8;      // f4 offset within 32-f4 row segment

    __syncthreads();

    for (int t = 0; t < STEPS; ++t) {
        const float* hin  = g_h + (t & 1) * BATCH * HID;
        float*       hout = g_h + ((t + 1) & 1) * BATCH * HID;
        const float* xwt  = g_xw + (size_t)t * BATCH * FOURH
                            + (size_t)ub * FOURH + cta * 4 + uu;

        // prefetch this step's xw gate biases (DRAM, hidden behind staging+GEMM)
        float x0 = __ldcs(xwt);
        float x1 = __ldcs(xwt + 512);
        float x2 = __ldcs(xwt + 1024);
        float x3 = __ldcs(xwt + 1536);

        // issue all 4 k-chunk loads (32 KB each) as separate commit groups
#pragma unroll
        for (int c = 0; c < 4; ++c) {
            const float* src = hin + sb * HID + c * 128 + soff * 4;
            unsigned     dst = hs_u32 + (sb * HID + c * 128 + soff * 4) * 4;
#pragma unroll
            for (int j = 0; j < 8; ++j)
                cpasync16(dst + j * 16, src + j * 4);
            asm volatile("cp.async.commit_group;");
        }

        unsigned long long acc[8];
#pragma unroll
        for (int j = 0; j < 8; ++j) acc[j] = 0ull;

        // consume chunk c while chunks c+1.. stream in
#define LSTM_CHUNK(C, W)                                                      \
        {                                                                     \
            cpasync_wait<W>();                                                \
            __syncthreads();                                                  \
            _Pragma("unroll 4")                                               \
            for (int it = (C) * 16; it < (C) * 16 + 16; ++it) {               \
                float4 wv = *(const float4*)(wp + it * 128);                  \
                unsigned long long w0 = f4lo(wv), w1 = f4hi(wv);              \
                _Pragma("unroll")                                             \
                for (int j = 0; j < 8; ++j) {                                 \
                    float4 hv = *(const float4*)(hrow + j * HID + it * 8);    \
                    fma2(acc[j], f4lo(hv), w0);                               \
                    fma2(acc[j], f4hi(hv), w1);                               \
                }                                                             \
            }                                                                 \
        }
        LSTM_CHUNK(0, 3)
        LSTM_CHUNK(1, 2)
        LSTM_CHUNK(2, 1)
        LSTM_CHUNK(3, 0)
#undef LSTM_CHUNK

        // reduce the two k-halves (lane ^ 16) and write pre-activations
        float part[8];
#pragma unroll
        for (int j = 0; j < 8; ++j) {
            float p = hsum2(acc[j]);
            p += __shfl_xor_sync(0xffffffffu, p, 16);
            part[j] = p;
        }
        if (kq == 0) {
#pragma unroll
            for (int j = 0; j < 8; ++j)
                spre[col * 65 + wrp * 8 + j] = part[j];
        }
        __syncthreads();

        // cell update: thread -> (b = tid>>2, u = tid&3); c in register
        {
            float pi = spre[(0  + uu) * 65 + ub] + x0;
            float pf = spre[(4  + uu) * 65 + ub] + x1;
            float pg = spre[(8  + uu) * 65 + ub] + x2;
            float po = spre[(12 + uu) * 65 + ub] + x3;
            float ig = fsigmoid_(pi);
            float fg = fsigmoid_(pf);
            float gg = ftanh_(pg);
            float og = fsigmoid_(po);
            creg = fg * creg + ig * gg;
            float hh = og * ftanh_(creg);
            __stcg(&hout[ub * HID + cta * 4 + uu], hh);
        }
        grid_barrier(nct, (unsigned)(t + 1));
    }
}

#define SMEM_LSTM ((8192 + 32768 + 16 * 65) * 4)

// ---------------- kernel 3: out = h_final @ Wout^T + bout ---------------------
__global__ __launch_bounds__(256, 4) void outproj_kernel(
    const float* __restrict__ Wout, const float* __restrict__ bout,
    float* __restrict__ out) {
    __shared__ float As[2][16][68];
    __shared__ float Bs[2][16][68];

    const int tid = threadIdx.x;
    const int n0 = blockIdx.x * 64;
    const int tn = tid & 15, tb = tid >> 4;
    const float* h = g_h;  // final h lives in buffer 0 (STEPS even)

    const int arow = tid >> 2, ac4 = tid & 3;

    unsigned long long acc[4][2];
#pragma unroll
    for (int i = 0; i < 4; ++i) { acc[i][0] = 0ull; acc[i][1] = 0ull; }

    float4 pa = make_float4(0.f, 0.f, 0.f, 0.f);
    if (n0 + arow < NCLASS) pa = *(const float4*)(Wout + (size_t)(n0 + arow) * HID + ac4 * 4);
    float4 pbv = *(const float4*)(h + arow * HID + ac4 * 4);

    int cur = 0;
    for (int kt = 0; kt < HID; kt += 16) {
        As[cur][ac4 * 4 + 0][arow] = pa.x;
        As[cur][ac4 * 4 + 1][arow] = pa.y;
        As[cur][ac4 * 4 + 2][arow] = pa.z;
        As[cur][ac4 * 4 + 3][arow] = pa.w;
        Bs[cur][ac4 * 4 + 0][arow] = pbv.x;
        Bs[cur][ac4 * 4 + 1][arow] = pbv.y;
        Bs[cur][ac4 * 4 + 2][arow] = pbv.z;
        Bs[cur][ac4 * 4 + 3][arow] = pbv.w;
        if (kt + 16 < HID) {
            int kn = kt + 16;
            pa = make_float4(0.f, 0.f, 0.f, 0.f);
            if (n0 + arow < NCLASS) pa = *(const float4*)(Wout + (size_t)(n0 + arow) * HID + kn + ac4 * 4);
            pbv = *(const float4*)(h + arow * HID + kn + ac4 * 4);
        }
        __syncthreads();
#pragma unroll
        for (int kk = 0; kk < 16; ++kk) {
            float4 av = *(const float4*)&As[cur][kk][tn * 4];
            float4 bv = *(const float4*)&Bs[cur][kk][tb * 4];
            unsigned long long bp0 = f4lo(bv), bp1 = f4hi(bv);
            float avv[4] = {av.x, av.y, av.z, av.w};
#pragma unroll
            for (int i = 0; i < 4; ++i) {
                unsigned long long ad = pack2(avv[i], avv[i]);
                fma2(acc[i][0], ad, bp0);
                fma2(acc[i][1], ad, bp1);
            }
        }
        cur ^= 1;
    }

#pragma unroll
    for (int i = 0; i < 4; ++i) {
        int n = n0 + tn * 4 + i;
        if (n >= NCLASS) continue;
        float bo = bout[n];
        float2 v0 = unpack2(acc[i][0]);
        float2 v1 = unpack2(acc[i][1]);
        out[(size_t)(tb * 4 + 0) * NCLASS + n] = v0.x + bo;
        out[(size_t)(tb * 4 + 1) * NCLASS + n] = v0.y + bo;
        out[(size_t)(tb * 4 + 2) * NCLASS + n] = v1.x + bo;
        out[(size_t)(tb * 4 + 3) * NCLASS + n] = v1.y + bo;
    }
}

// ---------------- launch --------------------------------------------------------
extern "C" void kernel_launch(void* const* d_in, const int* in_sizes, int n_in,
                              void* d_out, int out_size) {
    const int*   X    = (const int*)d_in[0];
    const float* emb  = (const float*)d_in[1];
    const float* Wi   = (const float*)d_in[2];
    const float* Wh   = (const float*)d_in[3];
    const float* bi   = (const float*)d_in[4];
    const float* bh   = (const float*)d_in[5];
    // d_in[6..9]: layer-2 params — provably unused by the reference output
    const float* Wout = (const float*)d_in[10];
    const float* bout = (const float*)d_in[11];
    float* out = (float*)d_out;

    // allow >48KB dynamic smem (attribute set, not an allocation; idempotent)
    cudaFuncSetAttribute(lstm_kernel,
                         cudaFuncAttributeMaxDynamicSharedMemorySize, SMEM_LSTM);

    prep_kernel<<<64, 256>>>(bi, bh);
    xw_gemm_kernel<<<dim3(FOURH / 128, (STEPS * BATCH) / 128), 256>>>(X, emb, Wi);
    lstm_kernel<<<128, 256, SMEM_LSTM>>>(Wh);
    outproj_kernel<<<(NCLASS + 63) / 64, 256>>>(Wout, bout, out);
}

// round 8
// speedup vs baseline: 1.5410x; 1.5410x over previous
#include <cuda_runtime.h>
#include <cuda_bf16.h>
#include <cstdint>

#define EMB    512
#define HID    512
#define NCLASS 50257
#define BATCH  64
#define STEPS  256
#define FOURH  2048

// ---------------- scratch (device globals; no mallocs allowed) ---------------
__device__ float    g_xw[STEPS * BATCH * FOURH];   // 128 MiB precomputed input proj
__device__ float    g_h[2 * BATCH * HID];          // double-buffered hidden state
__device__ float    g_bsum[FOURH];                 // bi + bh
// barrier words on SEPARATE 128B L2 lines
__device__ __align__(128) unsigned g_barc[32];     // monotonic arrival counter
__device__ __align__(128) unsigned g_barp[32];     // monotonic phase

// ---------------- packed f32x2 helpers (sm_103a) ------------------------------
__device__ __forceinline__ unsigned long long pack2(float x, float y) {
    unsigned long long r;
    asm("mov.b64 %0, {%1, %2};" : "=l"(r) : "f"(x), "f"(y));
    return r;
}
__device__ __forceinline__ void fma2(unsigned long long& acc,
                                     unsigned long long a, unsigned long long b) {
    asm("fma.rn.f32x2 %0, %1, %2, %0;" : "+l"(acc) : "l"(a), "l"(b));
}
__device__ __forceinline__ float2 unpack2(unsigned long long v) {
    float2 f;
    asm("mov.b64 {%0, %1}, %2;" : "=f"(f.x), "=f"(f.y) : "l"(v));
    return f;
}
__device__ __forceinline__ float hsum2(unsigned long long v) {
    float2 f = unpack2(v);
    return f.x + f.y;
}
__device__ __forceinline__ unsigned long long f4lo(const float4& v) {
    return ((const unsigned long long*)&v)[0];
}
__device__ __forceinline__ unsigned long long f4hi(const float4& v) {
    return ((const unsigned long long*)&v)[1];
}
__device__ __forceinline__ float fsigmoid_(float x) {
    return __fdividef(1.0f, 1.0f + __expf(-x));
}
__device__ __forceinline__ float ftanh_(float x) {
    return 2.0f * __fdividef(1.0f, 1.0f + __expf(-2.0f * x)) - 1.0f;
}
__device__ __forceinline__ void cpasync16(unsigned dst, const void* src) {
    asm volatile("cp.async.cg.shared.global [%0], [%1], 16;"
                 :: "r"(dst), "l"(src) : "memory");
}
// tf32 helpers
__device__ __forceinline__ unsigned cvt_tf32(float v) {
    unsigned r;
    asm("cvt.rna.tf32.f32 %0, %1;" : "=r"(r) : "f"(v));
    return r;
}
__device__ __forceinline__ uint4 cvt_tf32x4(float4 v) {
    uint4 r;
    r.x = cvt_tf32(v.x); r.y = cvt_tf32(v.y);
    r.z = cvt_tf32(v.z); r.w = cvt_tf32(v.w);
    return r;
}
__device__ __forceinline__ void mma_tf32(float* c, const unsigned* a, const unsigned* b) {
    asm("mma.sync.aligned.m16n8k8.row.col.f32.tf32.tf32.f32 "
        "{%0,%1,%2,%3}, {%4,%5,%6,%7}, {%8,%9}, {%0,%1,%2,%3};"
        : "+f"(c[0]), "+f"(c[1]), "+f"(c[2]), "+f"(c[3])
        : "r"(a[0]), "r"(a[1]), "r"(a[2]), "r"(a[3]), "r"(b[0]), "r"(b[1]));
}

// ---------------- flat grid barrier (monotonic, release/acquire) --------------
__device__ __forceinline__ void grid_barrier(unsigned nct, unsigned target) {
    __syncthreads();
    if (threadIdx.x == 0) {
        unsigned old;
        asm volatile("atom.release.gpu.global.add.u32 %0, [%1], 1;"
                     : "=r"(old) : "l"(&g_barc[0]) : "memory");
        if (old + 1u == target * nct) {
            asm volatile("st.release.gpu.global.u32 [%0], %1;"
                         :: "l"(&g_barp[0]), "r"(target) : "memory");
        } else {
            unsigned cur;
            do {
                asm volatile("ld.acquire.gpu.global.u32 %0, [%1];"
                             : "=r"(cur) : "l"(&g_barp[0]) : "memory");
            } while (cur < target);
        }
    }
    __syncthreads();
}

// ---------------- kernel 0: prep ------------------------------------------------
__global__ void prep_kernel(const float* __restrict__ bi, const float* __restrict__ bh) {
    int i = blockIdx.x * blockDim.x + threadIdx.x;
    int stride = gridDim.x * blockDim.x;
    if (i < 32) { g_barc[i] = 0u; g_barp[i] = 0u; }
    if (i < FOURH) g_bsum[i] = bi[i] + bh[i];
    for (int j = i; j < 2 * BATCH * HID; j += stride) g_h[j] = 0.0f;
}

// ---------------- kernel 1: xw = gather(emb, X) @ Wi + bsum  (tf32 HMMA) -------
// CTA tile 128x128, K-tile 32, 8 warps as 2(m) x 4(n), warp tile 64x32,
// mma.m16n8k8 tf32, double-buffered smem with register prefetch.
// dyn smem: Asu[2][128][36] u32 | Bsu[2][32][132] u32
#define XW_AS(buf, r, k) sm_u[(buf) * 4608 + (r) * 36 + (k)]
#define XW_BS(buf, k, c) sm_u[9216 + (buf) * 4224 + (k) * 132 + (c)]
#define SMEM_XW ((9216 + 8448) * 4)

__global__ __launch_bounds__(256, 2) void xw_tf32_kernel(
    const int* __restrict__ X, const float* __restrict__ emb,
    const float* __restrict__ Wi) {
    extern __shared__ __align__(16) unsigned sm_u[];
    __shared__ int tok[128];

    const int tid = threadIdx.x;
    const int m0 = blockIdx.y * 128;
    const int n0 = blockIdx.x * 128;
    const int lane = tid & 31, wrp = tid >> 5;
    const int wm = wrp >> 2, wn = wrp & 3;           // warp grid 2x4
    const int g = lane >> 2, tig = lane & 3;

    // loader mappings
    const int arow_b = tid >> 3, akq = tid & 7;      // A: row base 0..31, k-quad
    const int bk_b   = tid >> 5, bc4 = tid & 31;     // B: k base 0..7, col-quad

    if (tid < 128) {
        int m = m0 + tid;
        tok[tid] = X[(m & 63) * STEPS + (m >> 6)];
    }
    __syncthreads();

    float acc[4][4][4];
#pragma unroll
    for (int mt = 0; mt < 4; ++mt)
#pragma unroll
        for (int nt = 0; nt < 4; ++nt)
#pragma unroll
            for (int j = 0; j < 4; ++j) acc[mt][nt][j] = 0.0f;

    // prefetch k-tile 0
    float4 pa[4], pb[4];
#pragma unroll
    for (int q = 0; q < 4; ++q) {
        pa[q] = *(const float4*)(emb + (size_t)tok[arow_b + q * 32] * EMB + akq * 4);
        pb[q] = *(const float4*)(Wi + (size_t)(bk_b + q * 8) * FOURH + n0 + bc4 * 4);
    }

    int cur = 0;
    for (int kt = 0; kt < EMB; kt += 32) {
        // store prefetched tile (cvt to tf32)
#pragma unroll
        for (int q = 0; q < 4; ++q) {
            *(uint4*)&XW_AS(cur, arow_b + q * 32, akq * 4) = cvt_tf32x4(pa[q]);
            *(uint4*)&XW_BS(cur, bk_b + q * 8, bc4 * 4)    = cvt_tf32x4(pb[q]);
        }
        if (kt + 32 < EMB) {
            int kn = kt + 32;
#pragma unroll
            for (int q = 0; q < 4; ++q) {
                pa[q] = *(const float4*)(emb + (size_t)tok[arow_b + q * 32] * EMB + kn + akq * 4);
                pb[q] = *(const float4*)(Wi + (size_t)(kn + bk_b + q * 8) * FOURH + n0 + bc4 * 4);
            }
        }
        __syncthreads();

#pragma unroll
        for (int k8 = 0; k8 < 4; ++k8) {
            const int k0 = k8 * 8;
            unsigned a[4][4], b[4][2];
#pragma unroll
            for (int mt = 0; mt < 4; ++mt) {
                int r = wm * 64 + mt * 16 + g;
                a[mt][0] = XW_AS(cur, r,     k0 + tig);
                a[mt][1] = XW_AS(cur, r + 8, k0 + tig);
                a[mt][2] = XW_AS(cur, r,     k0 + tig + 4);
                a[mt][3] = XW_AS(cur, r + 8, k0 + tig + 4);
            }
#pragma unroll
            for (int nt = 0; nt < 4; ++nt) {
                int c = wn * 32 + nt * 8 + g;
                b[nt][0] = XW_BS(cur, k0 + tig,     c);
                b[nt][1] = XW_BS(cur, k0 + tig + 4, c);
            }
#pragma unroll
            for (int mt = 0; mt < 4; ++mt)
#pragma unroll
                for (int nt = 0; nt < 4; ++nt)
                    mma_tf32(acc[mt][nt], a[mt], b[nt]);
        }
        cur ^= 1;
    }

    // epilogue: + bsum, store float2 pairs
    float bs0[4], bs1[4];
#pragma unroll
    for (int nt = 0; nt < 4; ++nt) {
        int c = n0 + wn * 32 + nt * 8 + tig * 2;
        bs0[nt] = g_bsum[c];
        bs1[nt] = g_bsum[c + 1];
    }
#pragma unroll
    for (int mt = 0; mt < 4; ++mt) {
        int r = m0 + wm * 64 + mt * 16 + g;
#pragma unroll
        for (int nt = 0; nt < 4; ++nt) {
            int c = n0 + wn * 32 + nt * 8 + tig * 2;
            *(float2*)(g_xw + (size_t)r * FOURH + c) =
                make_float2(acc[mt][nt][0] + bs0[nt], acc[mt][nt][1] + bs1[nt]);
            *(float2*)(g_xw + (size_t)(r + 8) * FOURH + c) =
                make_float2(acc[mt][nt][2] + bs0[nt], acc[mt][nt][3] + bs1[nt]);
        }
    }
}

// ---------------- kernel 2: persistent LSTM (R6 body, known-good) -------------
__global__ __launch_bounds__(256, 1) void lstm_kernel(const float* __restrict__ Wh) {
    extern __shared__ __align__(16) float sm[];
    float* w_s  = sm;                    // 8192 floats (32 KB)
    float* h_s  = sm + 8192;             // 32768 floats (128 KB)
    float* spre = sm + 8192 + 32768;     // 16*65 floats

    const int tid = threadIdx.x;
    const int cta = blockIdx.x;
    const unsigned nct = gridDim.x;
    const int lane = tid & 31, wrp = tid >> 5;

    for (int i = tid; i < 8192; i += 256) {
        int j  = i & 3;
        int ln = (i >> 2) & 31;
        int it = i >> 7;
        int c  = ln & 15;
        int k  = it * 8 + (ln >> 4) * 4 + j;
        int gcol = (c >> 2) * HID + cta * 4 + (c & 3);
        w_s[i] = Wh[(size_t)k * FOURH + gcol];
    }

    const int col = lane & 15, kq = lane >> 4;
    const int ub = tid >> 2, uu = tid & 3;
    float creg = 0.0f;

    const unsigned hs_u32 = (unsigned)__cvta_generic_to_shared(h_s);
    const float* hrow = h_s + wrp * 8 * HID + kq * 4;
    const float* wp   = w_s + lane * 4;

    __syncthreads();

    for (int t = 0; t < STEPS; ++t) {
        const float* hin  = g_h + (t & 1) * BATCH * HID;
        float*       hout = g_h + ((t + 1) & 1) * BATCH * HID;
        const float* xwt  = g_xw + (size_t)t * BATCH * FOURH
                            + (size_t)ub * FOURH + cta * 4 + uu;

        float x0 = __ldcs(xwt);
        float x1 = __ldcs(xwt + 512);
        float x2 = __ldcs(xwt + 1024);
        float x3 = __ldcs(xwt + 1536);

#pragma unroll
        for (int j = 0; j < 32; ++j) {
            int i = tid + j * 256;
            cpasync16(hs_u32 + i * 16, hin + i * 4);
        }
        asm volatile("cp.async.commit_group;");
        asm volatile("cp.async.wait_group 0;" ::: "memory");
        __syncthreads();

        unsigned long long acc[8];
#pragma unroll
        for (int j = 0; j < 8; ++j) acc[j] = 0ull;

#pragma unroll 4
        for (int it = 0; it < 64; ++it) {
            float4 wv = *(const float4*)(wp + it * 128);
            unsigned long long w0 = f4lo(wv), w1 = f4hi(wv);
#pragma unroll
            for (int j = 0; j < 8; ++j) {
                float4 hv = *(const float4*)(hrow + j * HID + it * 8);
                fma2(acc[j], f4lo(hv), w0);
                fma2(acc[j], f4hi(hv), w1);
            }
        }

        float part[8];
#pragma unroll
        for (int j = 0; j < 8; ++j) {
            float p = hsum2(acc[j]);
            p += __shfl_xor_sync(0xffffffffu, p, 16);
            part[j] = p;
        }
        if (kq == 0) {
#pragma unroll
            for (int j = 0; j < 8; ++j)
                spre[col * 65 + wrp * 8 + j] = part[j];
        }
        __syncthreads();

        {
            float pi = spre[(0  + uu) * 65 + ub] + x0;
            float pf = spre[(4  + uu) * 65 + ub] + x1;
            float pg = spre[(8  + uu) * 65 + ub] + x2;
            float po = spre[(12 + uu) * 65 + ub] + x3;
            float ig = fsigmoid_(pi);
            float fg = fsigmoid_(pf);
            float gg = ftanh_(pg);
            float og = fsigmoid_(po);
            creg = fg * creg + ig * gg;
            float hh = og * ftanh_(creg);
            __stcg(&hout[ub * HID + cta * 4 + uu], hh);
        }
        grid_barrier(nct, (unsigned)(t + 1));
    }
}

#define SMEM_LSTM ((8192 + 32768 + 16 * 65) * 4)

// ---------------- kernel 3: out = h_final @ Wout^T + bout ---------------------
__global__ __launch_bounds__(256, 4) void outproj_kernel(
    const float* __restrict__ Wout, const float* __restrict__ bout,
    float* __restrict__ out) {
    __shared__ float As[2][16][68];
    __shared__ float Bs[2][16][68];

    const int tid = threadIdx.x;
    const int n0 = blockIdx.x * 64;
    const int tn = tid & 15, tb = tid >> 4;
    const float* h = g_h;  // final h lives in buffer 0 (STEPS even)

    const int arow = tid >> 2, ac4 = tid & 3;

    unsigned long long acc[4][2];
#pragma unroll
    for (int i = 0; i < 4; ++i) { acc[i][0] = 0ull; acc[i][1] = 0ull; }

    float4 pa = make_float4(0.f, 0.f, 0.f, 0.f);
    if (n0 + arow < NCLASS) pa = *(const float4*)(Wout + (size_t)(n0 + arow) * HID + ac4 * 4);
    float4 pbv = *(const float4*)(h + arow * HID + ac4 * 4);

    int cur = 0;
    for (int kt = 0; kt < HID; kt += 16) {
        As[cur][ac4 * 4 + 0][arow] = pa.x;
        As[cur][ac4 * 4 + 1][arow] = pa.y;
        As[cur][ac4 * 4 + 2][arow] = pa.z;
        As[cur][ac4 * 4 + 3][arow] = pa.w;
        Bs[cur][ac4 * 4 + 0][arow] = pbv.x;
        Bs[cur][ac4 * 4 + 1][arow] = pbv.y;
        Bs[cur][ac4 * 4 + 2][arow] = pbv.z;
        Bs[cur][ac4 * 4 + 3][arow] = pbv.w;
        if (kt + 16 < HID) {
            int kn = kt + 16;
            pa = make_float4(0.f, 0.f, 0.f, 0.f);
            if (n0 + arow < NCLASS) pa = *(const float4*)(Wout + (size_t)(n0 + arow) * HID + kn + ac4 * 4);
            pbv = *(const float4*)(h + arow * HID + kn + ac4 * 4);
        }
        __syncthreads();
#pragma unroll
        for (int kk = 0; kk < 16; ++kk) {
            float4 av = *(const float4*)&As[cur][kk][tn * 4];
            float4 bv = *(const float4*)&Bs[cur][kk][tb * 4];
            unsigned long long bp0 = f4lo(bv), bp1 = f4hi(bv);
            float avv[4] = {av.x, av.y, av.z, av.w};
#pragma unroll
            for (int i = 0; i < 4; ++i) {
                unsigned long long ad = pack2(avv[i], avv[i]);
                fma2(acc[i][0], ad, bp0);
                fma2(acc[i][1], ad, bp1);
            }
        }
        cur ^= 1;
    }

#pragma unroll
    for (int i = 0; i < 4; ++i) {
        int n = n0 + tn * 4 + i;
        if (n >= NCLASS) continue;
        float bo = bout[n];
        float2 v0 = unpack2(acc[i][0]);
        float2 v1 = unpack2(acc[i][1]);
        out[(size_t)(tb * 4 + 0) * NCLASS + n] = v0.x + bo;
        out[(size_t)(tb * 4 + 1) * NCLASS + n] = v0.y + bo;
        out[(size_t)(tb * 4 + 2) * NCLASS + n] = v1.x + bo;
        out[(size_t)(tb * 4 + 3) * NCLASS + n] = v1.y + bo;
    }
}

// ---------------- launch --------------------------------------------------------
extern "C" void kernel_launch(void* const* d_in, const int* in_sizes, int n_in,
                              void* d_out, int out_size) {
    const int*   X    = (const int*)d_in[0];
    const float* emb  = (const float*)d_in[1];
    const float* Wi   = (const float*)d_in[2];
    const float* Wh   = (const float*)d_in[3];
    const float* bi   = (const float*)d_in[4];
    const float* bh   = (const float*)d_in[5];
    // d_in[6..9]: layer-2 params — provably unused by the reference output
    const float* Wout = (const float*)d_in[10];
    const float* bout = (const float*)d_in[11];
    float* out = (float*)d_out;

    // allow >48KB dynamic smem (attribute only, not an allocation; idempotent)
    cudaFuncSetAttribute(lstm_kernel,
                         cudaFuncAttributeMaxDynamicSharedMemorySize, SMEM_LSTM);
    cudaFuncSetAttribute(xw_tf32_kernel,
                         cudaFuncAttributeMaxDynamicSharedMemorySize, SMEM_XW);

    prep_kernel<<<64, 256>>>(bi, bh);
    xw_tf32_kernel<<<dim3(FOURH / 128, (STEPS * BATCH) / 128), 256, SMEM_XW>>>(X, emb, Wi);
    lstm_kernel<<<128, 256, SMEM_LSTM>>>(Wh);
    outproj_kernel<<<(NCLASS + 63) / 64, 256>>>(Wout, bout, out);
}

// round 9
// speedup vs baseline: 1.8971x; 1.2311x over previous
#include <cuda_runtime.h>
#include <cuda_bf16.h>
#include <cstdint>

#define EMB    512
#define HID    512
#define NCLASS 50257
#define BATCH  64
#define STEPS  256
#define FOURH  2048

// ---------------- scratch (device globals; no mallocs allowed) ---------------
__device__ float    g_xw[STEPS * BATCH * FOURH];   // 128 MiB precomputed input proj
__device__ float    g_h[2 * BATCH * HID];          // double-buffered hidden state
__device__ float    g_bsum[FOURH];                 // bi + bh
// barrier words on SEPARATE 128B L2 lines
__device__ __align__(128) unsigned g_barc[32];     // monotonic arrival counter
__device__ __align__(128) unsigned g_barp[32];     // monotonic phase

// ---------------- packed f32x2 helpers (sm_103a) ------------------------------
__device__ __forceinline__ unsigned long long pack2(float x, float y) {
    unsigned long long r;
    asm("mov.b64 %0, {%1, %2};" : "=l"(r) : "f"(x), "f"(y));
    return r;
}
__device__ __forceinline__ void fma2(unsigned long long& acc,
                                     unsigned long long a, unsigned long long b) {
    asm("fma.rn.f32x2 %0, %1, %2, %0;" : "+l"(acc) : "l"(a), "l"(b));
}
__device__ __forceinline__ float2 unpack2(unsigned long long v) {
    float2 f;
    asm("mov.b64 {%0, %1}, %2;" : "=f"(f.x), "=f"(f.y) : "l"(v));
    return f;
}
__device__ __forceinline__ unsigned long long f4lo(const float4& v) {
    return ((const unsigned long long*)&v)[0];
}
__device__ __forceinline__ unsigned long long f4hi(const float4& v) {
    return ((const unsigned long long*)&v)[1];
}
__device__ __forceinline__ float fsigmoid_(float x) {
    return __fdividef(1.0f, 1.0f + __expf(-x));
}
__device__ __forceinline__ float ftanh_(float x) {
    return 2.0f * __fdividef(1.0f, 1.0f + __expf(-2.0f * x)) - 1.0f;
}
__device__ __forceinline__ void cpasync16(unsigned dst, const void* src) {
    asm volatile("cp.async.cg.shared.global [%0], [%1], 16;"
                 :: "r"(dst), "l"(src) : "memory");
}
// tf32 helpers
__device__ __forceinline__ unsigned cvt_tf32(float v) {
    unsigned r;
    asm("cvt.rna.tf32.f32 %0, %1;" : "=r"(r) : "f"(v));
    return r;
}
__device__ __forceinline__ uint4 cvt_tf32x4(float4 v) {
    uint4 r;
    r.x = cvt_tf32(v.x); r.y = cvt_tf32(v.y);
    r.z = cvt_tf32(v.z); r.w = cvt_tf32(v.w);
    return r;
}
__device__ __forceinline__ void mma_tf32(float* c, const unsigned* a, const unsigned* b) {
    asm("mma.sync.aligned.m16n8k8.row.col.f32.tf32.tf32.f32 "
        "{%0,%1,%2,%3}, {%4,%5,%6,%7}, {%8,%9}, {%0,%1,%2,%3};"
        : "+f"(c[0]), "+f"(c[1]), "+f"(c[2]), "+f"(c[3])
        : "r"(a[0]), "r"(a[1]), "r"(a[2]), "r"(a[3]), "r"(b[0]), "r"(b[1]));
}

// ---------------- flat grid barrier (monotonic, release/acquire) --------------
__device__ __forceinline__ void grid_barrier(unsigned nct, unsigned target) {
    __syncthreads();
    if (threadIdx.x == 0) {
        unsigned old;
        asm volatile("atom.release.gpu.global.add.u32 %0, [%1], 1;"
                     : "=r"(old) : "l"(&g_barc[0]) : "memory");
        if (old + 1u == target * nct) {
            asm volatile("st.release.gpu.global.u32 [%0], %1;"
                         :: "l"(&g_barp[0]), "r"(target) : "memory");
        } else {
            unsigned cur;
            do {
                asm volatile("ld.acquire.gpu.global.u32 %0, [%1];"
                             : "=r"(cur) : "l"(&g_barp[0]) : "memory");
            } while (cur < target);
        }
    }
    __syncthreads();
}

// ---------------- kernel 0: prep ------------------------------------------------
__global__ void prep_kernel(const float* __restrict__ bi, const float* __restrict__ bh) {
    int i = blockIdx.x * blockDim.x + threadIdx.x;
    int stride = gridDim.x * blockDim.x;
    if (i < 32) { g_barc[i] = 0u; g_barp[i] = 0u; }
    if (i < FOURH) g_bsum[i] = bi[i] + bh[i];
    for (int j = i; j < 2 * BATCH * HID; j += stride) g_h[j] = 0.0f;
}

// ---------------- kernel 1: xw = gather(emb, X) @ Wi + bsum  (tf32 HMMA) -------
#define XW_AS(buf, r, k) sm_u[(buf) * 4608 + (r) * 36 + (k)]
#define XW_BS(buf, k, c) sm_u[9216 + (buf) * 4224 + (k) * 132 + (c)]
#define SMEM_XW ((9216 + 8448) * 4)

__global__ __launch_bounds__(256, 2) void xw_tf32_kernel(
    const int* __restrict__ X, const float* __restrict__ emb,
    const float* __restrict__ Wi) {
    extern __shared__ __align__(16) unsigned sm_u[];
    __shared__ int tok[128];

    const int tid = threadIdx.x;
    const int m0 = blockIdx.y * 128;
    const int n0 = blockIdx.x * 128;
    const int lane = tid & 31, wrp = tid >> 5;
    const int wm = wrp >> 2, wn = wrp & 3;
    const int g = lane >> 2, tig = lane & 3;

    const int arow_b = tid >> 3, akq = tid & 7;
    const int bk_b   = tid >> 5, bc4 = tid & 31;

    if (tid < 128) {
        int m = m0 + tid;
        tok[tid] = X[(m & 63) * STEPS + (m >> 6)];
    }
    __syncthreads();

    float acc[4][4][4];
#pragma unroll
    for (int mt = 0; mt < 4; ++mt)
#pragma unroll
        for (int nt = 0; nt < 4; ++nt)
#pragma unroll
            for (int j = 0; j < 4; ++j) acc[mt][nt][j] = 0.0f;

    float4 pa[4], pb[4];
#pragma unroll
    for (int q = 0; q < 4; ++q) {
        pa[q] = *(const float4*)(emb + (size_t)tok[arow_b + q * 32] * EMB + akq * 4);
        pb[q] = *(const float4*)(Wi + (size_t)(bk_b + q * 8) * FOURH + n0 + bc4 * 4);
    }

    int cur = 0;
    for (int kt = 0; kt < EMB; kt += 32) {
#pragma unroll
        for (int q = 0; q < 4; ++q) {
            *(uint4*)&XW_AS(cur, arow_b + q * 32, akq * 4) = cvt_tf32x4(pa[q]);
            *(uint4*)&XW_BS(cur, bk_b + q * 8, bc4 * 4)    = cvt_tf32x4(pb[q]);
        }
        if (kt + 32 < EMB) {
            int kn = kt + 32;
#pragma unroll
            for (int q = 0; q < 4; ++q) {
                pa[q] = *(const float4*)(emb + (size_t)tok[arow_b + q * 32] * EMB + kn + akq * 4);
                pb[q] = *(const float4*)(Wi + (size_t)(kn + bk_b + q * 8) * FOURH + n0 + bc4 * 4);
            }
        }
        __syncthreads();

#pragma unroll
        for (int k8 = 0; k8 < 4; ++k8) {
            const int k0 = k8 * 8;
            unsigned a[4][4], b[4][2];
#pragma unroll
            for (int mt = 0; mt < 4; ++mt) {
                int r = wm * 64 + mt * 16 + g;
                a[mt][0] = XW_AS(cur, r,     k0 + tig);
                a[mt][1] = XW_AS(cur, r + 8, k0 + tig);
                a[mt][2] = XW_AS(cur, r,     k0 + tig + 4);
                a[mt][3] = XW_AS(cur, r + 8, k0 + tig + 4);
            }
#pragma unroll
            for (int nt = 0; nt < 4; ++nt) {
                int c = wn * 32 + nt * 8 + g;
                b[nt][0] = XW_BS(cur, k0 + tig,     c);
                b[nt][1] = XW_BS(cur, k0 + tig + 4, c);
            }
#pragma unroll
            for (int mt = 0; mt < 4; ++mt)
#pragma unroll
                for (int nt = 0; nt < 4; ++nt)
                    mma_tf32(acc[mt][nt], a[mt], b[nt]);
        }
        cur ^= 1;
    }

    float bs0[4], bs1[4];
#pragma unroll
    for (int nt = 0; nt < 4; ++nt) {
        int c = n0 + wn * 32 + nt * 8 + tig * 2;
        bs0[nt] = g_bsum[c];
        bs1[nt] = g_bsum[c + 1];
    }
#pragma unroll
    for (int mt = 0; mt < 4; ++mt) {
        int r = m0 + wm * 64 + mt * 16 + g;
#pragma unroll
        for (int nt = 0; nt < 4; ++nt) {
            int c = n0 + wn * 32 + nt * 8 + tig * 2;
            *(float2*)(g_xw + (size_t)r * FOURH + c) =
                make_float2(acc[mt][nt][0] + bs0[nt], acc[mt][nt][1] + bs1[nt]);
            *(float2*)(g_xw + (size_t)(r + 8) * FOURH + c) =
                make_float2(acc[mt][nt][2] + bs0[nt], acc[mt][nt][3] + bs1[nt]);
        }
    }
}

// ---------------- kernel 2: persistent LSTM, 3xTF32 tensor-core GEMM ----------
// 128 CTAs = 64 col-groups x 2 batch-groups; 256 thr.
// CTA: 32 batches x 32 gate-cols (8 hidden units, 4 gates), K=512.
// Warps: mt(2, 16-batch) x ntp(2, 16-col) x kh(2, 256-k). 3-mma tf32 split
// (a_hi*b_hi + a_lo*b_hi + a_hi*b_lo) => ~fp32 precision.
// smem: h_s[32][516] f32 | wf_hi[64][4][64] u32 | wf_lo | spre2[2][32][33]
#define LSTM_SMEM ((16512 + 16384 + 16384 + 2112) * 4)

__global__ __launch_bounds__(256, 1) void lstm_tc_kernel(const float* __restrict__ Wh) {
    extern __shared__ __align__(16) float sm[];
    float*    h_s   = sm;                                  // [32][516]
    unsigned* wf_hi = (unsigned*)(sm + 16512);             // [64][4][64]
    unsigned* wf_lo = wf_hi + 16384;
    float*    spre2 = sm + 16512 + 32768;                  // [2][32][33]

    const int tid  = threadIdx.x;
    const int cta  = blockIdx.x;
    const unsigned nct = gridDim.x;
    const int colg = cta >> 1;          // 0..63 (8 hidden units each)
    const int bg   = cta & 1;           // batch half
    const int lane = tid & 31, wid = tid >> 5;
    const int g = lane >> 2, tig = lane & 3;
    const int mt = wid & 1, ntp = (wid >> 1) & 1, kh = wid >> 2;

    // one-time: split this CTA's 32 Wh columns into tf32 hi/lo fragment layout
    for (int idx = tid; idx < 16384; idx += 256) {
        int k8 = idx >> 8, nt = (idx >> 6) & 3, r = idx & 63;
        int gg = r >> 3, tg = (r >> 1) & 3, p = r & 1;
        int k  = k8 * 8 + tg + 4 * p;
        int c  = nt * 8 + gg;                       // local col 0..31
        int gc = (c >> 3) * HID + colg * 8 + (c & 7);
        float w = Wh[(size_t)k * FOURH + gc];
        unsigned hi = cvt_tf32(w);
        wf_hi[idx] = hi;
        wf_lo[idx] = cvt_tf32(w - __uint_as_float(hi));
    }

    const int ub = tid >> 3, uu = tid & 7;          // update: local batch, unit
    float creg = 0.0f;

    const unsigned hs_u32 = (unsigned)__cvta_generic_to_shared(h_s);
    const float* ha = h_s + (mt * 16 + g) * 516 + tig;
    const float* hb = ha + 8 * 516;

    __syncthreads();

    for (int t = 0; t < STEPS; ++t) {
        const float* hin  = g_h + (t & 1) * BATCH * HID;
        float*       hout = g_h + ((t + 1) & 1) * BATCH * HID;
        const float* xwt  = g_xw + (size_t)t * BATCH * FOURH
                            + (size_t)(bg * 32 + ub) * FOURH + colg * 8 + uu;

        // prefetch this step's xw gate biases
        float x0 = __ldcs(xwt);
        float x1 = __ldcs(xwt + 512);
        float x2 = __ldcs(xwt + 1024);
        float x3 = __ldcs(xwt + 1536);

        // stage this CTA's 32 batch rows of h (64 KB), padded rows (stride 516)
#pragma unroll
        for (int j = 0; j < 16; ++j) {
            int i = tid + j * 256;                  // f4 index; row=i>>7, cc=i&127
            int row = i >> 7, cc = i & 127;
            cpasync16(hs_u32 + (unsigned)(row * 516 + cc * 4) * 4,
                      hin + (size_t)(bg * 32 + row) * HID + cc * 4);
        }
        asm volatile("cp.async.commit_group;");
        asm volatile("cp.async.wait_group 0;" ::: "memory");
        __syncthreads();

        // 3xTF32 mma over this warp's k-half
        float acc0[4] = {0.f, 0.f, 0.f, 0.f};
        float acc1[4] = {0.f, 0.f, 0.f, 0.f};
#pragma unroll 4
        for (int k8 = kh * 32; k8 < kh * 32 + 32; ++k8) {
            const int k0 = k8 * 8;
            float av0 = ha[k0],     av1 = hb[k0];
            float av2 = ha[k0 + 4], av3 = hb[k0 + 4];
            unsigned a_hi[4], a_lo[4];
            a_hi[0] = cvt_tf32(av0); a_lo[0] = cvt_tf32(av0 - __uint_as_float(a_hi[0]));
            a_hi[1] = cvt_tf32(av1); a_lo[1] = cvt_tf32(av1 - __uint_as_float(a_hi[1]));
            a_hi[2] = cvt_tf32(av2); a_lo[2] = cvt_tf32(av2 - __uint_as_float(a_hi[2]));
            a_hi[3] = cvt_tf32(av3); a_lo[3] = cvt_tf32(av3 - __uint_as_float(a_hi[3]));

            const int wbase = (k8 * 4 + ntp * 2) * 64 + g * 8 + tig * 2;
            uint2 bh0 = *(const uint2*)&wf_hi[wbase];
            uint2 bl0 = *(const uint2*)&wf_lo[wbase];
            uint2 bh1 = *(const uint2*)&wf_hi[wbase + 64];
            uint2 bl1 = *(const uint2*)&wf_lo[wbase + 64];

            mma_tf32(acc0, a_hi, (const unsigned*)&bh0);
            mma_tf32(acc0, a_lo, (const unsigned*)&bh0);
            mma_tf32(acc0, a_hi, (const unsigned*)&bl0);
            mma_tf32(acc1, a_hi, (const unsigned*)&bh1);
            mma_tf32(acc1, a_lo, (const unsigned*)&bh1);
            mma_tf32(acc1, a_hi, (const unsigned*)&bl1);
        }

        // write per-k-half partial pre-activations: spre2[kh][col][batch]
        {
            float* sp = spre2 + kh * 1056;
            int b0 = mt * 16 + g;
            int c0 = ntp * 16 + tig * 2;
            sp[(c0)     * 33 + b0]     = acc0[0];
            sp[(c0 + 1) * 33 + b0]     = acc0[1];
            sp[(c0)     * 33 + b0 + 8] = acc0[2];
            sp[(c0 + 1) * 33 + b0 + 8] = acc0[3];
            sp[(c0 + 8) * 33 + b0]     = acc1[0];
            sp[(c0 + 9) * 33 + b0]     = acc1[1];
            sp[(c0 + 8) * 33 + b0 + 8] = acc1[2];
            sp[(c0 + 9) * 33 + b0 + 8] = acc1[3];
        }
        __syncthreads();

        // cell update: thread -> (local batch ub, unit uu)
        {
            float pi = spre2[(0  + uu) * 33 + ub] + spre2[1056 + (0  + uu) * 33 + ub] + x0;
            float pf = spre2[(8  + uu) * 33 + ub] + spre2[1056 + (8  + uu) * 33 + ub] + x1;
            float pg = spre2[(16 + uu) * 33 + ub] + spre2[1056 + (16 + uu) * 33 + ub] + x2;
            float po = spre2[(24 + uu) * 33 + ub] + spre2[1056 + (24 + uu) * 33 + ub] + x3;
            float ig = fsigmoid_(pi);
            float fg = fsigmoid_(pf);
            float gg = ftanh_(pg);
            float og = fsigmoid_(po);
            creg = fg * creg + ig * gg;
            float hh = og * ftanh_(creg);
            __stcg(&hout[(size_t)(bg * 32 + ub) * HID + colg * 8 + uu], hh);
        }
        grid_barrier(nct, (unsigned)(t + 1));
    }
}

// ---------------- kernel 3: out = h_final @ Wout^T + bout ---------------------
__global__ __launch_bounds__(256, 4) void outproj_kernel(
    const float* __restrict__ Wout, const float* __restrict__ bout,
    float* __restrict__ out) {
    __shared__ float As[2][16][68];
    __shared__ float Bs[2][16][68];

    const int tid = threadIdx.x;
    const int n0 = blockIdx.x * 64;
    const int tn = tid & 15, tb = tid >> 4;
    const float* h = g_h;  // final h lives in buffer 0 (STEPS even)

    const int arow = tid >> 2, ac4 = tid & 3;

    unsigned long long acc[4][2];
#pragma unroll
    for (int i = 0; i < 4; ++i) { acc[i][0] = 0ull; acc[i][1] = 0ull; }

    float4 pa = make_float4(0.f, 0.f, 0.f, 0.f);
    if (n0 + arow < NCLASS) pa = *(const float4*)(Wout + (size_t)(n0 + arow) * HID + ac4 * 4);
    float4 pbv = *(const float4*)(h + arow * HID + ac4 * 4);

    int cur = 0;
    for (int kt = 0; kt < HID; kt += 16) {
        As[cur][ac4 * 4 + 0][arow] = pa.x;
        As[cur][ac4 * 4 + 1][arow] = pa.y;
        As[cur][ac4 * 4 + 2][arow] = pa.z;
        As[cur][ac4 * 4 + 3][arow] = pa.w;
        Bs[cur][ac4 * 4 + 0][arow] = pbv.x;
        Bs[cur][ac4 * 4 + 1][arow] = pbv.y;
        Bs[cur][ac4 * 4 + 2][arow] = pbv.z;
        Bs[cur][ac4 * 4 + 3][arow] = pbv.w;
        if (kt + 16 < HID) {
            int kn = kt + 16;
            pa = make_float4(0.f, 0.f, 0.f, 0.f);
            if (n0 + arow < NCLASS) pa = *(const float4*)(Wout + (size_t)(n0 + arow) * HID + kn + ac4 * 4);
            pbv = *(const float4*)(h + arow * HID + kn + ac4 * 4);
        }
        __syncthreads();
#pragma unroll
        for (int kk = 0; kk < 16; ++kk) {
            float4 av = *(const float4*)&As[cur][kk][tn * 4];
            float4 bv = *(const float4*)&Bs[cur][kk][tb * 4];
            unsigned long long bp0 = f4lo(bv), bp1 = f4hi(bv);
            float avv[4] = {av.x, av.y, av.z, av.w};
#pragma unroll
            for (int i = 0; i < 4; ++i) {
                unsigned long long ad = pack2(avv[i], avv[i]);
                fma2(acc[i][0], ad, bp0);
                fma2(acc[i][1], ad, bp1);
            }
        }
        cur ^= 1;
    }

#pragma unroll
    for (int i = 0; i < 4; ++i) {
        int n = n0 + tn * 4 + i;
        if (n >= NCLASS) continue;
        float bo = bout[n];
        float2 v0 = unpack2(acc[i][0]);
        float2 v1 = unpack2(acc[i][1]);
        out[(size_t)(tb * 4 + 0) * NCLASS + n] = v0.x + bo;
        out[(size_t)(tb * 4 + 1) * NCLASS + n] = v0.y + bo;
        out[(size_t)(tb * 4 + 2) * NCLASS + n] = v1.x + bo;
        out[(size_t)(tb * 4 + 3) * NCLASS + n] = v1.y + bo;
    }
}

// ---------------- launch --------------------------------------------------------
extern "C" void kernel_launch(void* const* d_in, const int* in_sizes, int n_in,
                              void* d_out, int out_size) {
    const int*   X    = (const int*)d_in[0];
    const float* emb  = (const float*)d_in[1];
    const float* Wi   = (const float*)d_in[2];
    const float* Wh   = (const float*)d_in[3];
    const float* bi   = (const float*)d_in[4];
    const float* bh   = (const float*)d_in[5];
    // d_in[6..9]: layer-2 params — provably unused by the reference output
    const float* Wout = (const float*)d_in[10];
    const float* bout = (const float*)d_in[11];
    float* out = (float*)d_out;

    // allow >48KB dynamic smem (attribute only, not an allocation; idempotent)
    cudaFuncSetAttribute(lstm_tc_kernel,
                         cudaFuncAttributeMaxDynamicSharedMemorySize, LSTM_SMEM);
    cudaFuncSetAttribute(xw_tf32_kernel,
                         cudaFuncAttributeMaxDynamicSharedMemorySize, SMEM_XW);

    prep_kernel<<<64, 256>>>(bi, bh);
    xw_tf32_kernel<<<dim3(FOURH / 128, (STEPS * BATCH) / 128), 256, SMEM_XW>>>(X, emb, Wi);
    lstm_tc_kernel<<<128, 256, LSTM_SMEM>>>(Wh);
    outproj_kernel<<<(NCLASS + 63) / 64, 256>>>(Wout, bout, out);
}

// round 10
// speedup vs baseline: 2.4105x; 1.2707x over previous
#include <cuda_runtime.h>
#include <cuda_bf16.h>
#include <cstdint>

#define EMB    512
#define HID    512
#define NCLASS 50257
#define BATCH  64
#define STEPS  256
#define FOURH  2048

// ---------------- scratch (device globals; no mallocs allowed) ---------------
__device__ float    g_xw[STEPS * BATCH * FOURH];   // 128 MiB precomputed input proj
__device__ float    g_h[2 * BATCH * HID];          // double-buffered hidden state
__device__ float    g_bsum[FOURH];                 // bi + bh
// barrier words on SEPARATE 128B L2 lines
__device__ __align__(128) unsigned g_barc[32];     // monotonic arrival counter
__device__ __align__(128) unsigned g_barp[32];     // monotonic phase

// ---------------- packed f32x2 helpers (sm_103a) ------------------------------
__device__ __forceinline__ unsigned long long pack2(float x, float y) {
    unsigned long long r;
    asm("mov.b64 %0, {%1, %2};" : "=l"(r) : "f"(x), "f"(y));
    return r;
}
__device__ __forceinline__ void fma2(unsigned long long& acc,
                                     unsigned long long a, unsigned long long b) {
    asm("fma.rn.f32x2 %0, %1, %2, %0;" : "+l"(acc) : "l"(a), "l"(b));
}
__device__ __forceinline__ float2 unpack2(unsigned long long v) {
    float2 f;
    asm("mov.b64 {%0, %1}, %2;" : "=f"(f.x), "=f"(f.y) : "l"(v));
    return f;
}
__device__ __forceinline__ unsigned long long f4lo(const float4& v) {
    return ((const unsigned long long*)&v)[0];
}
__device__ __forceinline__ unsigned long long f4hi(const float4& v) {
    return ((const unsigned long long*)&v)[1];
}
__device__ __forceinline__ float fsigmoid_(float x) {
    return __fdividef(1.0f, 1.0f + __expf(-x));
}
__device__ __forceinline__ float ftanh_(float x) {
    return 2.0f * __fdividef(1.0f, 1.0f + __expf(-2.0f * x)) - 1.0f;
}
__device__ __forceinline__ void cpasync16(unsigned dst, const void* src) {
    asm volatile("cp.async.cg.shared.global [%0], [%1], 16;"
                 :: "r"(dst), "l"(src) : "memory");
}
// tf32 helpers
__device__ __forceinline__ unsigned cvt_tf32(float v) {
    unsigned r;
    asm("cvt.rna.tf32.f32 %0, %1;" : "=r"(r) : "f"(v));
    return r;
}
__device__ __forceinline__ uint4 cvt_tf32x4(float4 v) {
    uint4 r;
    r.x = cvt_tf32(v.x); r.y = cvt_tf32(v.y);
    r.z = cvt_tf32(v.z); r.w = cvt_tf32(v.w);
    return r;
}
__device__ __forceinline__ void mma_tf32(float* c, const unsigned* a, const unsigned* b) {
    asm("mma.sync.aligned.m16n8k8.row.col.f32.tf32.tf32.f32 "
        "{%0,%1,%2,%3}, {%4,%5,%6,%7}, {%8,%9}, {%0,%1,%2,%3};"
        : "+f"(c[0]), "+f"(c[1]), "+f"(c[2]), "+f"(c[3])
        : "r"(a[0]), "r"(a[1]), "r"(a[2]), "r"(a[3]), "r"(b[0]), "r"(b[1]));
}

// ---------------- flat grid barrier (monotonic, release/acquire) --------------
__device__ __forceinline__ void grid_barrier(unsigned nct, unsigned target) {
    __syncthreads();
    if (threadIdx.x == 0) {
        unsigned old;
        asm volatile("atom.release.gpu.global.add.u32 %0, [%1], 1;"
                     : "=r"(old) : "l"(&g_barc[0]) : "memory");
        if (old + 1u == target * nct) {
            asm volatile("st.release.gpu.global.u32 [%0], %1;"
                         :: "l"(&g_barp[0]), "r"(target) : "memory");
        } else {
            unsigned cur;
            do {
                asm volatile("ld.acquire.gpu.global.u32 %0, [%1];"
                             : "=r"(cur) : "l"(&g_barp[0]) : "memory");
            } while (cur < target);
        }
    }
    __syncthreads();
}

// ---------------- kernel 0: prep ------------------------------------------------
__global__ void prep_kernel(const float* __restrict__ bi, const float* __restrict__ bh) {
    int i = blockIdx.x * blockDim.x + threadIdx.x;
    int stride = gridDim.x * blockDim.x;
    if (i < 32) { g_barc[i] = 0u; g_barp[i] = 0u; }
    if (i < FOURH) g_bsum[i] = bi[i] + bh[i];
    for (int j = i; j < 2 * BATCH * HID; j += stride) g_h[j] = 0.0f;
}

// ---------------- kernel 1: xw = gather(emb, X) @ Wi + bsum  (tf32 HMMA) -------
#define XW_AS(buf, r, k) sm_u[(buf) * 4608 + (r) * 36 + (k)]
#define XW_BS(buf, k, c) sm_u[9216 + (buf) * 4224 + (k) * 132 + (c)]
#define SMEM_XW ((9216 + 8448) * 4)

__global__ __launch_bounds__(256, 2) void xw_tf32_kernel(
    const int* __restrict__ X, const float* __restrict__ emb,
    const float* __restrict__ Wi) {
    extern __shared__ __align__(16) unsigned sm_u[];
    __shared__ int tok[128];

    const int tid = threadIdx.x;
    const int m0 = blockIdx.y * 128;
    const int n0 = blockIdx.x * 128;
    const int lane = tid & 31, wrp = tid >> 5;
    const int wm = wrp >> 2, wn = wrp & 3;
    const int g = lane >> 2, tig = lane & 3;

    const int arow_b = tid >> 3, akq = tid & 7;
    const int bk_b   = tid >> 5, bc4 = tid & 31;

    if (tid < 128) {
        int m = m0 + tid;
        tok[tid] = X[(m & 63) * STEPS + (m >> 6)];
    }
    __syncthreads();

    float acc[4][4][4];
#pragma unroll
    for (int mt = 0; mt < 4; ++mt)
#pragma unroll
        for (int nt = 0; nt < 4; ++nt)
#pragma unroll
            for (int j = 0; j < 4; ++j) acc[mt][nt][j] = 0.0f;

    float4 pa[4], pb[4];
#pragma unroll
    for (int q = 0; q < 4; ++q) {
        pa[q] = *(const float4*)(emb + (size_t)tok[arow_b + q * 32] * EMB + akq * 4);
        pb[q] = *(const float4*)(Wi + (size_t)(bk_b + q * 8) * FOURH + n0 + bc4 * 4);
    }

    int cur = 0;
    for (int kt = 0; kt < EMB; kt += 32) {
#pragma unroll
        for (int q = 0; q < 4; ++q) {
            *(uint4*)&XW_AS(cur, arow_b + q * 32, akq * 4) = cvt_tf32x4(pa[q]);
            *(uint4*)&XW_BS(cur, bk_b + q * 8, bc4 * 4)    = cvt_tf32x4(pb[q]);
        }
        if (kt + 32 < EMB) {
            int kn = kt + 32;
#pragma unroll
            for (int q = 0; q < 4; ++q) {
                pa[q] = *(const float4*)(emb + (size_t)tok[arow_b + q * 32] * EMB + kn + akq * 4);
                pb[q] = *(const float4*)(Wi + (size_t)(kn + bk_b + q * 8) * FOURH + n0 + bc4 * 4);
            }
        }
        __syncthreads();

#pragma unroll
        for (int k8 = 0; k8 < 4; ++k8) {
            const int k0 = k8 * 8;
            unsigned a[4][4], b[4][2];
#pragma unroll
            for (int mt = 0; mt < 4; ++mt) {
                int r = wm * 64 + mt * 16 + g;
                a[mt][0] = XW_AS(cur, r,     k0 + tig);
                a[mt][1] = XW_AS(cur, r + 8, k0 + tig);
                a[mt][2] = XW_AS(cur, r,     k0 + tig + 4);
                a[mt][3] = XW_AS(cur, r + 8, k0 + tig + 4);
            }
#pragma unroll
            for (int nt = 0; nt < 4; ++nt) {
                int c = wn * 32 + nt * 8 + g;
                b[nt][0] = XW_BS(cur, k0 + tig,     c);
                b[nt][1] = XW_BS(cur, k0 + tig + 4, c);
            }
#pragma unroll
            for (int mt = 0; mt < 4; ++mt)
#pragma unroll
                for (int nt = 0; nt < 4; ++nt)
                    mma_tf32(acc[mt][nt], a[mt], b[nt]);
        }
        cur ^= 1;
    }

    float bs0[4], bs1[4];
#pragma unroll
    for (int nt = 0; nt < 4; ++nt) {
        int c = n0 + wn * 32 + nt * 8 + tig * 2;
        bs0[nt] = g_bsum[c];
        bs1[nt] = g_bsum[c + 1];
    }
#pragma unroll
    for (int mt = 0; mt < 4; ++mt) {
        int r = m0 + wm * 64 + mt * 16 + g;
#pragma unroll
        for (int nt = 0; nt < 4; ++nt) {
            int c = n0 + wn * 32 + nt * 8 + tig * 2;
            *(float2*)(g_xw + (size_t)r * FOURH + c) =
                make_float2(acc[mt][nt][0] + bs0[nt], acc[mt][nt][1] + bs1[nt]);
            *(float2*)(g_xw + (size_t)(r + 8) * FOURH + c) =
                make_float2(acc[mt][nt][2] + bs0[nt], acc[mt][nt][3] + bs1[nt]);
        }
    }
}

// ---------------- kernel 2: persistent LSTM, single-TF32 tensor-core GEMM -----
// 128 CTAs = 64 col-groups x 2 batch-groups; 256 thr.
// CTA: 32 batches x 32 gate-cols (8 hidden units, 4 gates), K=512.
// Warps: mt(2, 16-batch) x ntp(2, 16-col) x kh(2, 256-k). Single tf32 mma
// (same precision class as the xw path, measured 1.8e-6 end-to-end).
// smem: h_s[32][516] f32 | wf_hi[64][4][64] u32 | spre2[2][32][33]
#define LSTM_SMEM ((16512 + 16384 + 2112) * 4)

__global__ __launch_bounds__(256, 1) void lstm_tc_kernel(const float* __restrict__ Wh) {
    extern __shared__ __align__(16) float sm[];
    float*    h_s   = sm;                                  // [32][516]
    unsigned* wf_hi = (unsigned*)(sm + 16512);             // [64][4][64]
    float*    spre2 = sm + 16512 + 16384;                  // [2][32][33]

    const int tid  = threadIdx.x;
    const int cta  = blockIdx.x;
    const unsigned nct = gridDim.x;
    const int colg = cta >> 1;          // 0..63 (8 hidden units each)
    const int bg   = cta & 1;           // batch half
    const int lane = tid & 31, wid = tid >> 5;
    const int g = lane >> 2, tig = lane & 3;
    const int mt = wid & 1, ntp = (wid >> 1) & 1, kh = wid >> 2;

    // one-time: pack this CTA's 32 Wh columns into tf32 fragment layout
    for (int idx = tid; idx < 16384; idx += 256) {
        int k8 = idx >> 8, nt = (idx >> 6) & 3, r = idx & 63;
        int gg = r >> 3, tg = (r >> 1) & 3, p = r & 1;
        int k  = k8 * 8 + tg + 4 * p;
        int c  = nt * 8 + gg;                       // local col 0..31
        int gc = (c >> 3) * HID + colg * 8 + (c & 7);
        wf_hi[idx] = cvt_tf32(Wh[(size_t)k * FOURH + gc]);
    }

    const int ub = tid >> 3, uu = tid & 7;          // update: local batch, unit
    float creg = 0.0f;

    const unsigned hs_u32 = (unsigned)__cvta_generic_to_shared(h_s);
    const float* ha = h_s + (mt * 16 + g) * 516 + tig;
    const float* hb = ha + 8 * 516;

    __syncthreads();

    for (int t = 0; t < STEPS; ++t) {
        const float* hin  = g_h + (t & 1) * BATCH * HID;
        float*       hout = g_h + ((t + 1) & 1) * BATCH * HID;
        const float* xwt  = g_xw + (size_t)t * BATCH * FOURH
                            + (size_t)(bg * 32 + ub) * FOURH + colg * 8 + uu;

        // prefetch this step's xw gate biases
        float x0 = __ldcs(xwt);
        float x1 = __ldcs(xwt + 512);
        float x2 = __ldcs(xwt + 1024);
        float x3 = __ldcs(xwt + 1536);

        // stage this CTA's 32 batch rows of h (64 KB), padded rows (stride 516)
#pragma unroll
        for (int j = 0; j < 16; ++j) {
            int i = tid + j * 256;                  // f4 index; row=i>>7, cc=i&127
            int row = i >> 7, cc = i & 127;
            cpasync16(hs_u32 + (unsigned)(row * 516 + cc * 4) * 4,
                      hin + (size_t)(bg * 32 + row) * HID + cc * 4);
        }
        asm volatile("cp.async.commit_group;");
        asm volatile("cp.async.wait_group 0;" ::: "memory");
        __syncthreads();

        // single-tf32 mma over this warp's k-half
        float acc0[4] = {0.f, 0.f, 0.f, 0.f};
        float acc1[4] = {0.f, 0.f, 0.f, 0.f};
#pragma unroll 8
        for (int k8 = kh * 32; k8 < kh * 32 + 32; ++k8) {
            const int k0 = k8 * 8;
            unsigned a[4];
            a[0] = cvt_tf32(ha[k0]);
            a[1] = cvt_tf32(hb[k0]);
            a[2] = cvt_tf32(ha[k0 + 4]);
            a[3] = cvt_tf32(hb[k0 + 4]);

            const int wbase = (k8 * 4 + ntp * 2) * 64 + g * 8 + tig * 2;
            uint2 bh0 = *(const uint2*)&wf_hi[wbase];
            uint2 bh1 = *(const uint2*)&wf_hi[wbase + 64];

            mma_tf32(acc0, a, (const unsigned*)&bh0);
            mma_tf32(acc1, a, (const unsigned*)&bh1);
        }

        // write per-k-half partial pre-activations: spre2[kh][col][batch]
        {
            float* sp = spre2 + kh * 1056;
            int b0 = mt * 16 + g;
            int c0 = ntp * 16 + tig * 2;
            sp[(c0)     * 33 + b0]     = acc0[0];
            sp[(c0 + 1) * 33 + b0]     = acc0[1];
            sp[(c0)     * 33 + b0 + 8] = acc0[2];
            sp[(c0 + 1) * 33 + b0 + 8] = acc0[3];
            sp[(c0 + 8) * 33 + b0]     = acc1[0];
            sp[(c0 + 9) * 33 + b0]     = acc1[1];
            sp[(c0 + 8) * 33 + b0 + 8] = acc1[2];
            sp[(c0 + 9) * 33 + b0 + 8] = acc1[3];
        }
        __syncthreads();

        // cell update: thread -> (local batch ub, unit uu)
        {
            float pi = spre2[(0  + uu) * 33 + ub] + spre2[1056 + (0  + uu) * 33 + ub] + x0;
            float pf = spre2[(8  + uu) * 33 + ub] + spre2[1056 + (8  + uu) * 33 + ub] + x1;
            float pg = spre2[(16 + uu) * 33 + ub] + spre2[1056 + (16 + uu) * 33 + ub] + x2;
            float po = spre2[(24 + uu) * 33 + ub] + spre2[1056 + (24 + uu) * 33 + ub] + x3;
            float ig = fsigmoid_(pi);
            float fg = fsigmoid_(pf);
            float gg = ftanh_(pg);
            float og = fsigmoid_(po);
            creg = fg * creg + ig * gg;
            float hh = og * ftanh_(creg);
            __stcg(&hout[(size_t)(bg * 32 + ub) * HID + colg * 8 + uu], hh);
        }
        grid_barrier(nct, (unsigned)(t + 1));
    }
}

// ---------------- kernel 3: out = h_final @ Wout^T + bout ---------------------
__global__ __launch_bounds__(256, 4) void outproj_kernel(
    const float* __restrict__ Wout, const float* __restrict__ bout,
    float* __restrict__ out) {
    __shared__ float As[2][16][68];
    __shared__ float Bs[2][16][68];

    const int tid = threadIdx.x;
    const int n0 = blockIdx.x * 64;
    const int tn = tid & 15, tb = tid >> 4;
    const float* h = g_h;  // final h lives in buffer 0 (STEPS even)

    const int arow = tid >> 2, ac4 = tid & 3;

    unsigned long long acc[4][2];
#pragma unroll
    for (int i = 0; i < 4; ++i) { acc[i][0] = 0ull; acc[i][1] = 0ull; }

    float4 pa = make_float4(0.f, 0.f, 0.f, 0.f);
    if (n0 + arow < NCLASS) pa = *(const float4*)(Wout + (size_t)(n0 + arow) * HID + ac4 * 4);
    float4 pbv = *(const float4*)(h + arow * HID + ac4 * 4);

    int cur = 0;
    for (int kt = 0; kt < HID; kt += 16) {
        As[cur][ac4 * 4 + 0][arow] = pa.x;
        As[cur][ac4 * 4 + 1][arow] = pa.y;
        As[cur][ac4 * 4 + 2][arow] = pa.z;
        As[cur][ac4 * 4 + 3][arow] = pa.w;
        Bs[cur][ac4 * 4 + 0][arow] = pbv.x;
        Bs[cur][ac4 * 4 + 1][arow] = pbv.y;
        Bs[cur][ac4 * 4 + 2][arow] = pbv.z;
        Bs[cur][ac4 * 4 + 3][arow] = pbv.w;
        if (kt + 16 < HID) {
            int kn = kt + 16;
            pa = make_float4(0.f, 0.f, 0.f, 0.f);
            if (n0 + arow < NCLASS) pa = *(const float4*)(Wout + (size_t)(n0 + arow) * HID + kn + ac4 * 4);
            pbv = *(const float4*)(h + arow * HID + kn + ac4 * 4);
        }
        __syncthreads();
#pragma unroll
        for (int kk = 0; kk < 16; ++kk) {
            float4 av = *(const float4*)&As[cur][kk][tn * 4];
            float4 bv = *(const float4*)&Bs[cur][kk][tb * 4];
            unsigned long long bp0 = f4lo(bv), bp1 = f4hi(bv);
            float avv[4] = {av.x, av.y, av.z, av.w};
#pragma unroll
            for (int i = 0; i < 4; ++i) {
                unsigned long long ad = pack2(avv[i], avv[i]);
                fma2(acc[i][0], ad, bp0);
                fma2(acc[i][1], ad, bp1);
            }
        }
        cur ^= 1;
    }

#pragma unroll
    for (int i = 0; i < 4; ++i) {
        int n = n0 + tn * 4 + i;
        if (n >= NCLASS) continue;
        float bo = bout[n];
        float2 v0 = unpack2(acc[i][0]);
        float2 v1 = unpack2(acc[i][1]);
        out[(size_t)(tb * 4 + 0) * NCLASS + n] = v0.x + bo;
        out[(size_t)(tb * 4 + 1) * NCLASS + n] = v0.y + bo;
        out[(size_t)(tb * 4 + 2) * NCLASS + n] = v1.x + bo;
        out[(size_t)(tb * 4 + 3) * NCLASS + n] = v1.y + bo;
    }
}

// ---------------- launch --------------------------------------------------------
extern "C" void kernel_launch(void* const* d_in, const int* in_sizes, int n_in,
                              void* d_out, int out_size) {
    const int*   X    = (const int*)d_in[0];
    const float* emb  = (const float*)d_in[1];
    const float* Wi   = (const float*)d_in[2];
    const float* Wh   = (const float*)d_in[3];
    const float* bi   = (const float*)d_in[4];
    const float* bh   = (const float*)d_in[5];
    // d_in[6..9]: layer-2 params — provably unused by the reference output
    const float* Wout = (const float*)d_in[10];
    const float* bout = (const float*)d_in[11];
    float* out = (float*)d_out;

    // allow >48KB dynamic smem (attribute only, not an allocation; idempotent)
    cudaFuncSetAttribute(lstm_tc_kernel,
                         cudaFuncAttributeMaxDynamicSharedMemorySize, LSTM_SMEM);
    cudaFuncSetAttribute(xw_tf32_kernel,
                         cudaFuncAttributeMaxDynamicSharedMemorySize, SMEM_XW);

    prep_kernel<<<64, 256>>>(bi, bh);
    xw_tf32_kernel<<<dim3(FOURH / 128, (STEPS * BATCH) / 128), 256, SMEM_XW>>>(X, emb, Wi);
    lstm_tc_kernel<<<128, 256, LSTM_SMEM>>>(Wh);
    outproj_kernel<<<(NCLASS + 63) / 64, 256>>>(Wout, bout, out);
}

// round 11
// speedup vs baseline: 2.9057x; 1.2054x over previous
#include <cuda_runtime.h>
#include <cuda_bf16.h>
#include <cstdint>

#define EMB    512
#define HID    512
#define NCLASS 50257
#define BATCH  64
#define STEPS  256
#define FOURH  2048

// ---------------- scratch (device globals; no mallocs allowed) ---------------
__device__ float          g_xw[STEPS * BATCH * FOURH]; // 128 MiB input proj
__device__ __nv_bfloat16  g_h[2 * BATCH * HID];        // double-buffered h (bf16)
__device__ float          g_hf[BATCH * HID];           // fp32 h at final step
__device__ float          g_bsum[FOURH];               // bi + bh
// barrier words on SEPARATE 128B L2 lines
__device__ __align__(128) unsigned g_barc[32];
__device__ __align__(128) unsigned g_barp[32];

// ---------------- packed f32x2 helpers (sm_103a) ------------------------------
__device__ __forceinline__ unsigned long long pack2(float x, float y) {
    unsigned long long r;
    asm("mov.b64 %0, {%1, %2};" : "=l"(r) : "f"(x), "f"(y));
    return r;
}
__device__ __forceinline__ void fma2(unsigned long long& acc,
                                     unsigned long long a, unsigned long long b) {
    asm("fma.rn.f32x2 %0, %1, %2, %0;" : "+l"(acc) : "l"(a), "l"(b));
}
__device__ __forceinline__ float2 unpack2(unsigned long long v) {
    float2 f;
    asm("mov.b64 {%0, %1}, %2;" : "=f"(f.x), "=f"(f.y) : "l"(v));
    return f;
}
__device__ __forceinline__ unsigned long long f4lo(const float4& v) {
    return ((const unsigned long long*)&v)[0];
}
__device__ __forceinline__ unsigned long long f4hi(const float4& v) {
    return ((const unsigned long long*)&v)[1];
}
__device__ __forceinline__ float fsigmoid_(float x) {
    return __fdividef(1.0f, 1.0f + __expf(-x));
}
__device__ __forceinline__ float ftanh_(float x) {
    return 2.0f * __fdividef(1.0f, 1.0f + __expf(-2.0f * x)) - 1.0f;
}
__device__ __forceinline__ void cpasync16(unsigned dst, const void* src) {
    asm volatile("cp.async.cg.shared.global [%0], [%1], 16;"
                 :: "r"(dst), "l"(src) : "memory");
}
// tf32 helpers (xw kernel)
__device__ __forceinline__ unsigned cvt_tf32(float v) {
    unsigned r;
    asm("cvt.rna.tf32.f32 %0, %1;" : "=r"(r) : "f"(v));
    return r;
}
__device__ __forceinline__ uint4 cvt_tf32x4(float4 v) {
    uint4 r;
    r.x = cvt_tf32(v.x); r.y = cvt_tf32(v.y);
    r.z = cvt_tf32(v.z); r.w = cvt_tf32(v.w);
    return r;
}
__device__ __forceinline__ void mma_tf32(float* c, const unsigned* a, const unsigned* b) {
    asm("mma.sync.aligned.m16n8k8.row.col.f32.tf32.tf32.f32 "
        "{%0,%1,%2,%3}, {%4,%5,%6,%7}, {%8,%9}, {%0,%1,%2,%3};"
        : "+f"(c[0]), "+f"(c[1]), "+f"(c[2]), "+f"(c[3])
        : "r"(a[0]), "r"(a[1]), "r"(a[2]), "r"(a[3]), "r"(b[0]), "r"(b[1]));
}
// bf16 helpers (lstm kernel)
__device__ __forceinline__ unsigned pack_bf16(float lo, float hi) {
    unsigned r;
    asm("cvt.rn.bf16x2.f32 %0, %1, %2;" : "=r"(r) : "f"(hi), "f"(lo));
    return r;
}
__device__ __forceinline__ void mma_bf16(float* c, const unsigned* a, const unsigned* b) {
    asm("mma.sync.aligned.m16n8k16.row.col.f32.bf16.bf16.f32 "
        "{%0,%1,%2,%3}, {%4,%5,%6,%7}, {%8,%9}, {%0,%1,%2,%3};"
        : "+f"(c[0]), "+f"(c[1]), "+f"(c[2]), "+f"(c[3])
        : "r"(a[0]), "r"(a[1]), "r"(a[2]), "r"(a[3]), "r"(b[0]), "r"(b[1]));
}

// ---------------- flat grid barrier (monotonic, release/acquire) --------------
__device__ __forceinline__ void grid_barrier(unsigned nct, unsigned target) {
    __syncthreads();
    if (threadIdx.x == 0) {
        unsigned old;
        asm volatile("atom.release.gpu.global.add.u32 %0, [%1], 1;"
                     : "=r"(old) : "l"(&g_barc[0]) : "memory");
        if (old + 1u == target * nct) {
            asm volatile("st.release.gpu.global.u32 [%0], %1;"
                         :: "l"(&g_barp[0]), "r"(target) : "memory");
        } else {
            unsigned cur;
            do {
                asm volatile("ld.acquire.gpu.global.u32 %0, [%1];"
                             : "=r"(cur) : "l"(&g_barp[0]) : "memory");
            } while (cur < target);
        }
    }
    __syncthreads();
}

// ---------------- kernel 0: prep ------------------------------------------------
__global__ void prep_kernel(const float* __restrict__ bi, const float* __restrict__ bh) {
    int i = blockIdx.x * blockDim.x + threadIdx.x;
    int stride = gridDim.x * blockDim.x;
    if (i < 32) { g_barc[i] = 0u; g_barp[i] = 0u; }
    if (i < FOURH) g_bsum[i] = bi[i] + bh[i];
    unsigned* gh = (unsigned*)g_h;                 // 2*64*512 bf16 = 32768 u32
    for (int j = i; j < 32768; j += stride) gh[j] = 0u;
}

// ---------------- kernel 1: xw = gather(emb, X) @ Wi + bsum  (tf32 HMMA) -------
#define XW_AS(buf, r, k) sm_u[(buf) * 4608 + (r) * 36 + (k)]
#define XW_BS(buf, k, c) sm_u[9216 + (buf) * 4224 + (k) * 132 + (c)]
#define SMEM_XW ((9216 + 8448) * 4)

__global__ __launch_bounds__(256, 2) void xw_tf32_kernel(
    const int* __restrict__ X, const float* __restrict__ emb,
    const float* __restrict__ Wi) {
    extern __shared__ __align__(16) unsigned sm_u[];
    __shared__ int tok[128];

    const int tid = threadIdx.x;
    const int m0 = blockIdx.y * 128;
    const int n0 = blockIdx.x * 128;
    const int lane = tid & 31, wrp = tid >> 5;
    const int wm = wrp >> 2, wn = wrp & 3;
    const int g = lane >> 2, tig = lane & 3;

    const int arow_b = tid >> 3, akq = tid & 7;
    const int bk_b   = tid >> 5, bc4 = tid & 31;

    if (tid < 128) {
        int m = m0 + tid;
        tok[tid] = X[(m & 63) * STEPS + (m >> 6)];
    }
    __syncthreads();

    float acc[4][4][4];
#pragma unroll
    for (int mt = 0; mt < 4; ++mt)
#pragma unroll
        for (int nt = 0; nt < 4; ++nt)
#pragma unroll
            for (int j = 0; j < 4; ++j) acc[mt][nt][j] = 0.0f;

    float4 pa[4], pb[4];
#pragma unroll
    for (int q = 0; q < 4; ++q) {
        pa[q] = *(const float4*)(emb + (size_t)tok[arow_b + q * 32] * EMB + akq * 4);
        pb[q] = *(const float4*)(Wi + (size_t)(bk_b + q * 8) * FOURH + n0 + bc4 * 4);
    }

    int cur = 0;
    for (int kt = 0; kt < EMB; kt += 32) {
#pragma unroll
        for (int q = 0; q < 4; ++q) {
            *(uint4*)&XW_AS(cur, arow_b + q * 32, akq * 4) = cvt_tf32x4(pa[q]);
            *(uint4*)&XW_BS(cur, bk_b + q * 8, bc4 * 4)    = cvt_tf32x4(pb[q]);
        }
        if (kt + 32 < EMB) {
            int kn = kt + 32;
#pragma unroll
            for (int q = 0; q < 4; ++q) {
                pa[q] = *(const float4*)(emb + (size_t)tok[arow_b + q * 32] * EMB + kn + akq * 4);
                pb[q] = *(const float4*)(Wi + (size_t)(kn + bk_b + q * 8) * FOURH + n0 + bc4 * 4);
            }
        }
        __syncthreads();

#pragma unroll
        for (int k8 = 0; k8 < 4; ++k8) {
            const int k0 = k8 * 8;
            unsigned a[4][4], b[4][2];
#pragma unroll
            for (int mt = 0; mt < 4; ++mt) {
                int r = wm * 64 + mt * 16 + g;
                a[mt][0] = XW_AS(cur, r,     k0 + tig);
                a[mt][1] = XW_AS(cur, r + 8, k0 + tig);
                a[mt][2] = XW_AS(cur, r,     k0 + tig + 4);
                a[mt][3] = XW_AS(cur, r + 8, k0 + tig + 4);
            }
#pragma unroll
            for (int nt = 0; nt < 4; ++nt) {
                int c = wn * 32 + nt * 8 + g;
                b[nt][0] = XW_BS(cur, k0 + tig,     c);
                b[nt][1] = XW_BS(cur, k0 + tig + 4, c);
            }
#pragma unroll
            for (int mt = 0; mt < 4; ++mt)
#pragma unroll
                for (int nt = 0; nt < 4; ++nt)
                    mma_tf32(acc[mt][nt], a[mt], b[nt]);
        }
        cur ^= 1;
    }

    float bs0[4], bs1[4];
#pragma unroll
    for (int nt = 0; nt < 4; ++nt) {
        int c = n0 + wn * 32 + nt * 8 + tig * 2;
        bs0[nt] = g_bsum[c];
        bs1[nt] = g_bsum[c + 1];
    }
#pragma unroll
    for (int mt = 0; mt < 4; ++mt) {
        int r = m0 + wm * 64 + mt * 16 + g;
#pragma unroll
        for (int nt = 0; nt < 4; ++nt) {
            int c = n0 + wn * 32 + nt * 8 + tig * 2;
            *(float2*)(g_xw + (size_t)r * FOURH + c) =
                make_float2(acc[mt][nt][0] + bs0[nt], acc[mt][nt][1] + bs1[nt]);
            *(float2*)(g_xw + (size_t)(r + 8) * FOURH + c) =
                make_float2(acc[mt][nt][2] + bs0[nt], acc[mt][nt][3] + bs1[nt]);
        }
    }
}

// ---------------- kernel 2: persistent LSTM, bf16 m16n8k16 tensor-core GEMM ---
// 128 CTAs = 64 col-groups x 2 batch-groups; 256 thr.
// CTA: 32 batches x 32 gate-cols, K=512. Warps: mt(2) x ntp(2) x kh(2).
// h exchanged in bf16 (32 KB staged/CTA); fp32 h copy written at final step.
// smem (u32): h_s[32][260] | wf[32][4][32][2] | spre2 (f32 2112)
#define LSTM_SMEM ((8320 + 8192 + 2112) * 4)

__global__ __launch_bounds__(256, 1) void lstm_bf16_kernel(const float* __restrict__ Wh) {
    extern __shared__ __align__(16) unsigned smu[];
    unsigned* h_s   = smu;                     // [32][260] u32 (bf16x2 pairs)
    unsigned* wf    = smu + 8320;              // [32 k16][4 nt][32 lane][2]
    float*    spre2 = (float*)(smu + 8320 + 8192);  // [2][32][33]

    const int tid  = threadIdx.x;
    const int cta  = blockIdx.x;
    const unsigned nct = gridDim.x;
    const int colg = cta >> 1;          // 0..63 (8 hidden units each)
    const int bg   = cta & 1;           // batch half
    const int lane = tid & 31, wid = tid >> 5;
    const int g = lane >> 2, tig = lane & 3;
    const int mt = wid & 1, ntp = (wid >> 1) & 1, kh = wid >> 2;

    // one-time: pack this CTA's 32 Wh columns into bf16 B-fragment layout
    for (int idx = tid; idx < 8192; idx += 256) {
        int reg = idx & 1;
        int ln  = (idx >> 1) & 31;
        int nt  = (idx >> 6) & 3;
        int i16 = idx >> 8;                     // k16 tile 0..31
        int lg = ln >> 2, ltig = ln & 3;
        int k0 = i16 * 16 + 2 * ltig + reg * 8;
        int c  = nt * 8 + lg;                   // local col 0..31
        int gc = (c >> 3) * HID + colg * 8 + (c & 7);
        wf[idx] = pack_bf16(Wh[(size_t)k0 * FOURH + gc],
                            Wh[(size_t)(k0 + 1) * FOURH + gc]);
    }

    const int ub = tid >> 3, uu = tid & 7;      // update: local batch, unit
    float creg = 0.0f;

    const unsigned hs_addr = (unsigned)__cvta_generic_to_shared(h_s);
    const unsigned* ha = h_s + (mt * 16 + g) * 260 + tig;
    const unsigned* hb = ha + 8 * 260;

    __syncthreads();

    for (int t = 0; t < STEPS; ++t) {
        const __nv_bfloat16* hin = g_h + (t & 1) * BATCH * HID;
        __nv_bfloat16*      hout = g_h + ((t + 1) & 1) * BATCH * HID;
        const float* xwt = g_xw + (size_t)t * BATCH * FOURH
                           + (size_t)(bg * 32 + ub) * FOURH + colg * 8 + uu;

        // prefetch this step's xw gate biases
        float x0 = __ldcs(xwt);
        float x1 = __ldcs(xwt + 512);
        float x2 = __ldcs(xwt + 1024);
        float x3 = __ldcs(xwt + 1536);

        // stage 32 bf16 h rows (32 KB), row stride 1040 B (pad breaks conflicts)
#pragma unroll
        for (int j = 0; j < 8; ++j) {
            int i = tid + j * 256;              // 16B chunk id 0..2047
            int row = i >> 6, cc = i & 63;
            cpasync16(hs_addr + (unsigned)(row * 1040 + cc * 16),
                      (const char*)hin + (size_t)(bg * 32 + row) * 1024 + cc * 16);
        }
        asm volatile("cp.async.commit_group;");
        asm volatile("cp.async.wait_group 0;" ::: "memory");
        __syncthreads();

        // bf16 mma over this warp's k-half (16 k16-tiles)
        float acc0[4] = {0.f, 0.f, 0.f, 0.f};
        float acc1[4] = {0.f, 0.f, 0.f, 0.f};
#pragma unroll 8
        for (int i16 = kh * 16; i16 < kh * 16 + 16; ++i16) {
            unsigned a[4];
            a[0] = ha[i16 * 8];
            a[1] = hb[i16 * 8];
            a[2] = ha[i16 * 8 + 4];
            a[3] = hb[i16 * 8 + 4];
            const unsigned* wb = wf + ((i16 * 4 + ntp * 2) * 32 + lane) * 2;
            uint2 b0 = *(const uint2*)wb;
            uint2 b1 = *(const uint2*)(wb + 64);
            mma_bf16(acc0, a, (const unsigned*)&b0);
            mma_bf16(acc1, a, (const unsigned*)&b1);
        }

        // write per-k-half partial pre-activations: spre2[kh][col][batch]
        {
            float* sp = spre2 + kh * 1056;
            int b0 = mt * 16 + g;
            int c0 = ntp * 16 + tig * 2;
            sp[(c0)     * 33 + b0]     = acc0[0];
            sp[(c0 + 1) * 33 + b0]     = acc0[1];
            sp[(c0)     * 33 + b0 + 8] = acc0[2];
            sp[(c0 + 1) * 33 + b0 + 8] = acc0[3];
            sp[(c0 + 8) * 33 + b0]     = acc1[0];
            sp[(c0 + 9) * 33 + b0]     = acc1[1];
            sp[(c0 + 8) * 33 + b0 + 8] = acc1[2];
            sp[(c0 + 9) * 33 + b0 + 8] = acc1[3];
        }
        __syncthreads();

        // cell update: thread -> (local batch ub, unit uu)
        {
            float pi = spre2[(0  + uu) * 33 + ub] + spre2[1056 + (0  + uu) * 33 + ub] + x0;
            float pf = spre2[(8  + uu) * 33 + ub] + spre2[1056 + (8  + uu) * 33 + ub] + x1;
            float pg = spre2[(16 + uu) * 33 + ub] + spre2[1056 + (16 + uu) * 33 + ub] + x2;
            float po = spre2[(24 + uu) * 33 + ub] + spre2[1056 + (24 + uu) * 33 + ub] + x3;
            float ig = fsigmoid_(pi);
            float fg = fsigmoid_(pf);
            float gg = ftanh_(pg);
            float og = fsigmoid_(po);
            creg = fg * creg + ig * gg;
            float hh = og * ftanh_(creg);
            size_t hidx = (size_t)(bg * 32 + ub) * HID + colg * 8 + uu;
            hout[hidx] = __float2bfloat16(hh);
            if (t == STEPS - 1) g_hf[hidx] = hh;   // fp32 copy for outproj
        }
        grid_barrier(nct, (unsigned)(t + 1));
    }
}

// ---------------- kernel 3: out = h_final @ Wout^T + bout ---------------------
__global__ __launch_bounds__(256, 4) void outproj_kernel(
    const float* __restrict__ Wout, const float* __restrict__ bout,
    float* __restrict__ out) {
    __shared__ float As[2][16][68];
    __shared__ float Bs[2][16][68];

    const int tid = threadIdx.x;
    const int n0 = blockIdx.x * 64;
    const int tn = tid & 15, tb = tid >> 4;
    const float* h = g_hf;   // fp32 final h

    const int arow = tid >> 2, ac4 = tid & 3;

    unsigned long long acc[4][2];
#pragma unroll
    for (int i = 0; i < 4; ++i) { acc[i][0] = 0ull; acc[i][1] = 0ull; }

    float4 pa = make_float4(0.f, 0.f, 0.f, 0.f);
    if (n0 + arow < NCLASS) pa = *(const float4*)(Wout + (size_t)(n0 + arow) * HID + ac4 * 4);
    float4 pbv = *(const float4*)(h + arow * HID + ac4 * 4);

    int cur = 0;
    for (int kt = 0; kt < HID; kt += 16) {
        As[cur][ac4 * 4 + 0][arow] = pa.x;
        As[cur][ac4 * 4 + 1][arow] = pa.y;
        As[cur][ac4 * 4 + 2][arow] = pa.z;
        As[cur][ac4 * 4 + 3][arow] = pa.w;
        Bs[cur][ac4 * 4 + 0][arow] = pbv.x;
        Bs[cur][ac4 * 4 + 1][arow] = pbv.y;
        Bs[cur][ac4 * 4 + 2][arow] = pbv.z;
        Bs[cur][ac4 * 4 + 3][arow] = pbv.w;
        if (kt + 16 < HID) {
            int kn = kt + 16;
            pa = make_float4(0.f, 0.f, 0.f, 0.f);
            if (n0 + arow < NCLASS) pa = *(const float4*)(Wout + (size_t)(n0 + arow) * HID + kn + ac4 * 4);
            pbv = *(const float4*)(h + arow * HID + kn + ac4 * 4);
        }
        __syncthreads();
#pragma unroll
        for (int kk = 0; kk < 16; ++kk) {
            float4 av = *(const float4*)&As[cur][kk][tn * 4];
            float4 bv = *(const float4*)&Bs[cur][kk][tb * 4];
            unsigned long long bp0 = f4lo(bv), bp1 = f4hi(bv);
            float avv[4] = {av.x, av.y, av.z, av.w};
#pragma unroll
            for (int i = 0; i < 4; ++i) {
                unsigned long long ad = pack2(avv[i], avv[i]);
                fma2(acc[i][0], ad, bp0);
                fma2(acc[i][1], ad, bp1);
            }
        }
        cur ^= 1;
    }

#pragma unroll
    for (int i = 0; i < 4; ++i) {
        int n = n0 + tn * 4 + i;
        if (n >= NCLASS) continue;
        float bo = bout[n];
        float2 v0 = unpack2(acc[i][0]);
        float2 v1 = unpack2(acc[i][1]);
        out[(size_t)(tb * 4 + 0) * NCLASS + n] = v0.x + bo;
        out[(size_t)(tb * 4 + 1) * NCLASS + n] = v0.y + bo;
        out[(size_t)(tb * 4 + 2) * NCLASS + n] = v1.x + bo;
        out[(size_t)(tb * 4 + 3) * NCLASS + n] = v1.y + bo;
    }
}

// ---------------- launch --------------------------------------------------------
extern "C" void kernel_launch(void* const* d_in, const int* in_sizes, int n_in,
                              void* d_out, int out_size) {
    const int*   X    = (const int*)d_in[0];
    const float* emb  = (const float*)d_in[1];
    const float* Wi   = (const float*)d_in[2];
    const float* Wh   = (const float*)d_in[3];
    const float* bi   = (const float*)d_in[4];
    const float* bh   = (const float*)d_in[5];
    // d_in[6..9]: layer-2 params — provably unused by the reference output
    const float* Wout = (const float*)d_in[10];
    const float* bout = (const float*)d_in[11];
    float* out = (float*)d_out;

    // allow >48KB dynamic smem (attribute only, not an allocation; idempotent)
    cudaFuncSetAttribute(lstm_bf16_kernel,
                         cudaFuncAttributeMaxDynamicSharedMemorySize, LSTM_SMEM);
    cudaFuncSetAttribute(xw_tf32_kernel,
                         cudaFuncAttributeMaxDynamicSharedMemorySize, SMEM_XW);

    prep_kernel<<<64, 256>>>(bi, bh);
    xw_tf32_kernel<<<dim3(FOURH / 128, (STEPS * BATCH) / 128), 256, SMEM_XW>>>(X, emb, Wi);
    lstm_bf16_kernel<<<128, 256, LSTM_SMEM>>>(Wh);
    outproj_kernel<<<(NCLASS + 63) / 64, 256>>>(Wout, bout, out);
}

// round 12
// speedup vs baseline: 3.1749x; 1.0927x over previous
#include <cuda_runtime.h>
#include <cuda_bf16.h>
#include <cstdint>

#define EMB    512
#define HID    512
#define NCLASS 50257
#define BATCH  64
#define STEPS  256
#define FOURH  2048

// ---------------- scratch (device globals; no mallocs allowed) ---------------
__device__ float          g_xw[STEPS * BATCH * FOURH]; // 128 MiB input proj
__device__ __nv_bfloat16  g_h[2 * BATCH * HID];        // double-buffered h (bf16)
__device__ float          g_hf[BATCH * HID];           // fp32 h at final step
__device__ float          g_bsum[FOURH];               // bi + bh
// 4 independent barrier domains; each counter/phase on its own 128B line
__device__ __align__(128) unsigned g_barc[4 * 32];
__device__ __align__(128) unsigned g_barp[4 * 32];

// ---------------- packed f32x2 helpers (sm_103a) ------------------------------
__device__ __forceinline__ unsigned long long pack2(float x, float y) {
    unsigned long long r;
    asm("mov.b64 %0, {%1, %2};" : "=l"(r) : "f"(x), "f"(y));
    return r;
}
__device__ __forceinline__ void fma2(unsigned long long& acc,
                                     unsigned long long a, unsigned long long b) {
    asm("fma.rn.f32x2 %0, %1, %2, %0;" : "+l"(acc) : "l"(a), "l"(b));
}
__device__ __forceinline__ float2 unpack2(unsigned long long v) {
    float2 f;
    asm("mov.b64 {%0, %1}, %2;" : "=f"(f.x), "=f"(f.y) : "l"(v));
    return f;
}
__device__ __forceinline__ unsigned long long f4lo(const float4& v) {
    return ((const unsigned long long*)&v)[0];
}
__device__ __forceinline__ unsigned long long f4hi(const float4& v) {
    return ((const unsigned long long*)&v)[1];
}
__device__ __forceinline__ float fsigmoid_(float x) {
    return __fdividef(1.0f, 1.0f + __expf(-x));
}
__device__ __forceinline__ float ftanh_(float x) {
    return 2.0f * __fdividef(1.0f, 1.0f + __expf(-2.0f * x)) - 1.0f;
}
__device__ __forceinline__ void cpasync16(unsigned dst, const void* src) {
    asm volatile("cp.async.cg.shared.global [%0], [%1], 16;"
                 :: "r"(dst), "l"(src) : "memory");
}
// tf32 helpers (xw kernel)
__device__ __forceinline__ unsigned cvt_tf32(float v) {
    unsigned r;
    asm("cvt.rna.tf32.f32 %0, %1;" : "=r"(r) : "f"(v));
    return r;
}
__device__ __forceinline__ uint4 cvt_tf32x4(float4 v) {
    uint4 r;
    r.x = cvt_tf32(v.x); r.y = cvt_tf32(v.y);
    r.z = cvt_tf32(v.z); r.w = cvt_tf32(v.w);
    return r;
}
__device__ __forceinline__ void mma_tf32(float* c, const unsigned* a, const unsigned* b) {
    asm("mma.sync.aligned.m16n8k8.row.col.f32.tf32.tf32.f32 "
        "{%0,%1,%2,%3}, {%4,%5,%6,%7}, {%8,%9}, {%0,%1,%2,%3};"
        : "+f"(c[0]), "+f"(c[1]), "+f"(c[2]), "+f"(c[3])
        : "r"(a[0]), "r"(a[1]), "r"(a[2]), "r"(a[3]), "r"(b[0]), "r"(b[1]));
}
// bf16 helpers (lstm kernel)
__device__ __forceinline__ unsigned pack_bf16(float lo, float hi) {
    unsigned r;
    asm("cvt.rn.bf16x2.f32 %0, %1, %2;" : "=r"(r) : "f"(hi), "f"(lo));
    return r;
}
__device__ __forceinline__ void mma_bf16(float* c, const unsigned* a, const unsigned* b) {
    asm("mma.sync.aligned.m16n8k16.row.col.f32.bf16.bf16.f32 "
        "{%0,%1,%2,%3}, {%4,%5,%6,%7}, {%8,%9}, {%0,%1,%2,%3};"
        : "+f"(c[0]), "+f"(c[1]), "+f"(c[2]), "+f"(c[3])
        : "r"(a[0]), "r"(a[1]), "r"(a[2]), "r"(a[3]), "r"(b[0]), "r"(b[1]));
}

// ---------------- per-domain grid barrier (32 CTAs each) -----------------------
__device__ __forceinline__ void domain_barrier(int dom, unsigned target) {
    __syncthreads();
    if (threadIdx.x == 0) {
        unsigned* cp = &g_barc[dom * 32];
        unsigned* pp = &g_barp[dom * 32];
        unsigned old;
        asm volatile("atom.release.gpu.global.add.u32 %0, [%1], 1;"
                     : "=r"(old) : "l"(cp) : "memory");
        if (old + 1u == target * 32u) {
            asm volatile("st.release.gpu.global.u32 [%0], %1;"
                         :: "l"(pp), "r"(target) : "memory");
        } else {
            unsigned cur;
            do {
                asm volatile("ld.acquire.gpu.global.u32 %0, [%1];"
                             : "=r"(cur) : "l"(pp) : "memory");
            } while (cur < target);
        }
    }
    __syncthreads();
}

// ---------------- kernel 0: prep ------------------------------------------------
__global__ void prep_kernel(const float* __restrict__ bi, const float* __restrict__ bh) {
    int i = blockIdx.x * blockDim.x + threadIdx.x;
    int stride = gridDim.x * blockDim.x;
    if (i < 128) { g_barc[i] = 0u; g_barp[i] = 0u; }
    if (i < FOURH) g_bsum[i] = bi[i] + bh[i];
    unsigned* gh = (unsigned*)g_h;                 // 2*64*512 bf16 = 32768 u32
    for (int j = i; j < 32768; j += stride) gh[j] = 0u;
}

// ---------------- kernel 1: xw = gather(emb, X) @ Wi + bsum  (tf32 HMMA) -------
#define XW_AS(buf, r, k) sm_u[(buf) * 4608 + (r) * 36 + (k)]
#define XW_BS(buf, k, c) sm_u[9216 + (buf) * 4224 + (k) * 132 + (c)]
#define SMEM_XW ((9216 + 8448) * 4)

__global__ __launch_bounds__(256, 2) void xw_tf32_kernel(
    const int* __restrict__ X, const float* __restrict__ emb,
    const float* __restrict__ Wi) {
    extern __shared__ __align__(16) unsigned sm_u[];
    __shared__ int tok[128];

    const int tid = threadIdx.x;
    const int m0 = blockIdx.y * 128;
    const int n0 = blockIdx.x * 128;
    const int lane = tid & 31, wrp = tid >> 5;
    const int wm = wrp >> 2, wn = wrp & 3;
    const int g = lane >> 2, tig = lane & 3;

    const int arow_b = tid >> 3, akq = tid & 7;
    const int bk_b   = tid >> 5, bc4 = tid & 31;

    if (tid < 128) {
        int m = m0 + tid;
        tok[tid] = X[(m & 63) * STEPS + (m >> 6)];
    }
    __syncthreads();

    float acc[4][4][4];
#pragma unroll
    for (int mt = 0; mt < 4; ++mt)
#pragma unroll
        for (int nt = 0; nt < 4; ++nt)
#pragma unroll
            for (int j = 0; j < 4; ++j) acc[mt][nt][j] = 0.0f;

    float4 pa[4], pb[4];
#pragma unroll
    for (int q = 0; q < 4; ++q) {
        pa[q] = *(const float4*)(emb + (size_t)tok[arow_b + q * 32] * EMB + akq * 4);
        pb[q] = *(const float4*)(Wi + (size_t)(bk_b + q * 8) * FOURH + n0 + bc4 * 4);
    }

    int cur = 0;
    for (int kt = 0; kt < EMB; kt += 32) {
#pragma unroll
        for (int q = 0; q < 4; ++q) {
            *(uint4*)&XW_AS(cur, arow_b + q * 32, akq * 4) = cvt_tf32x4(pa[q]);
            *(uint4*)&XW_BS(cur, bk_b + q * 8, bc4 * 4)    = cvt_tf32x4(pb[q]);
        }
        if (kt + 32 < EMB) {
            int kn = kt + 32;
#pragma unroll
            for (int q = 0; q < 4; ++q) {
                pa[q] = *(const float4*)(emb + (size_t)tok[arow_b + q * 32] * EMB + kn + akq * 4);
                pb[q] = *(const float4*)(Wi + (size_t)(kn + bk_b + q * 8) * FOURH + n0 + bc4 * 4);
            }
        }
        __syncthreads();

#pragma unroll
        for (int k8 = 0; k8 < 4; ++k8) {
            const int k0 = k8 * 8;
            unsigned a[4][4], b[4][2];
#pragma unroll
            for (int mt = 0; mt < 4; ++mt) {
                int r = wm * 64 + mt * 16 + g;
                a[mt][0] = XW_AS(cur, r,     k0 + tig);
                a[mt][1] = XW_AS(cur, r + 8, k0 + tig);
                a[mt][2] = XW_AS(cur, r,     k0 + tig + 4);
                a[mt][3] = XW_AS(cur, r + 8, k0 + tig + 4);
            }
#pragma unroll
            for (int nt = 0; nt < 4; ++nt) {
                int c = wn * 32 + nt * 8 + g;
                b[nt][0] = XW_BS(cur, k0 + tig,     c);
                b[nt][1] = XW_BS(cur, k0 + tig + 4, c);
            }
#pragma unroll
            for (int mt = 0; mt < 4; ++mt)
#pragma unroll
                for (int nt = 0; nt < 4; ++nt)
                    mma_tf32(acc[mt][nt], a[mt], b[nt]);
        }
        cur ^= 1;
    }

    float bs0[4], bs1[4];
#pragma unroll
    for (int nt = 0; nt < 4; ++nt) {
        int c = n0 + wn * 32 + nt * 8 + tig * 2;
        bs0[nt] = g_bsum[c];
        bs1[nt] = g_bsum[c + 1];
    }
#pragma unroll
    for (int mt = 0; mt < 4; ++mt) {
        int r = m0 + wm * 64 + mt * 16 + g;
#pragma unroll
        for (int nt = 0; nt < 4; ++nt) {
            int c = n0 + wn * 32 + nt * 8 + tig * 2;
            *(float2*)(g_xw + (size_t)r * FOURH + c) =
                make_float2(acc[mt][nt][0] + bs0[nt], acc[mt][nt][1] + bs1[nt]);
            *(float2*)(g_xw + (size_t)(r + 8) * FOURH + c) =
                make_float2(acc[mt][nt][2] + bs0[nt], acc[mt][nt][3] + bs1[nt]);
        }
    }
}

// ---------------- kernel 2: persistent LSTM, bf16 mma, 4 barrier domains ------
// 128 CTAs = 32 col-groups (16 hidden units = 64 gate cols) x 4 batch-groups(16).
// CTA tile: 16 batches x 64 gate cols, K=512. Warps: ntp(4, 16-col) x kh(2).
// Only same-bg CTAs exchange h -> 4 independent 32-CTA barriers.
// smem (u32): h_s[16][260] | wf[32 i16][8 nt][32 ln][2] | spre2 f32[2][64][17]
#define LSTM_SMEM ((4160 + 16384 + 2176) * 4)

__global__ __launch_bounds__(256, 1) void lstm_bf16_kernel(const float* __restrict__ Wh) {
    extern __shared__ __align__(16) unsigned smu[];
    unsigned* h_s   = smu;                          // [16][260] u32 (bf16x2)
    unsigned* wf    = smu + 4160;                   // [32][8][32][2]
    float*    spre2 = (float*)(smu + 4160 + 16384); // [2][64][17]

    const int tid  = threadIdx.x;
    const int cta  = blockIdx.x;
    const int colg = cta >> 2;          // 0..31 (16 hidden units each)
    const int bg   = cta & 3;           // batch quarter (barrier domain)
    const int lane = tid & 31, wid = tid >> 5;
    const int g = lane >> 2, tig = lane & 3;
    const int ntp = wid & 3, kh = wid >> 2;

    // one-time: pack this CTA's 64 Wh columns into bf16 B-fragment layout
    for (int idx = tid; idx < 16384; idx += 256) {
        int reg = idx & 1;
        int ln  = (idx >> 1) & 31;
        int nt8 = (idx >> 6) & 7;               // n-tile 0..7
        int i16 = idx >> 9;                     // k16 tile 0..31
        int lg = ln >> 2, ltig = ln & 3;
        int k0 = i16 * 16 + 2 * ltig + reg * 8;
        int c  = nt8 * 8 + lg;                  // local col 0..63
        int gc = (c >> 4) * HID + colg * 16 + (c & 15);
        wf[idx] = pack_bf16(Wh[(size_t)k0 * FOURH + gc],
                            Wh[(size_t)(k0 + 1) * FOURH + gc]);
    }

    const int ub = tid >> 4, uu = tid & 15;     // update: local batch, unit
    float creg = 0.0f;

    const unsigned hs_addr = (unsigned)__cvta_generic_to_shared(h_s);
    const unsigned* ha = h_s + g * 260 + tig;
    const unsigned* hb = ha + 8 * 260;

    __syncthreads();

    for (int t = 0; t < STEPS; ++t) {
        const __nv_bfloat16* hin = g_h + (t & 1) * BATCH * HID;
        __nv_bfloat16*      hout = g_h + ((t + 1) & 1) * BATCH * HID;
        const float* xwt = g_xw + (size_t)t * BATCH * FOURH
                           + (size_t)(bg * 16 + ub) * FOURH + colg * 16 + uu;

        // prefetch this step's xw gate biases
        float x0 = __ldcs(xwt);
        float x1 = __ldcs(xwt + 512);
        float x2 = __ldcs(xwt + 1024);
        float x3 = __ldcs(xwt + 1536);

        // stage 16 bf16 h rows (16 KB), row stride 1040 B
#pragma unroll
        for (int j = 0; j < 4; ++j) {
            int i = tid + j * 256;              // 16B chunk 0..1023
            int row = i >> 6, cc = i & 63;
            cpasync16(hs_addr + (unsigned)(row * 1040 + cc * 16),
                      (const char*)hin + (size_t)(bg * 16 + row) * 1024 + cc * 16);
        }
        asm volatile("cp.async.commit_group;");
        asm volatile("cp.async.wait_group 0;" ::: "memory");
        __syncthreads();

        // bf16 mma over this warp's k-half (16 k16-tiles, 2 n-tiles)
        float acc0[4] = {0.f, 0.f, 0.f, 0.f};
        float acc1[4] = {0.f, 0.f, 0.f, 0.f};
#pragma unroll 8
        for (int i16 = kh * 16; i16 < kh * 16 + 16; ++i16) {
            unsigned a[4];
            a[0] = ha[i16 * 8];
            a[1] = hb[i16 * 8];
            a[2] = ha[i16 * 8 + 4];
            a[3] = hb[i16 * 8 + 4];
            const unsigned* wb = wf + ((i16 * 8 + ntp * 2) * 32 + lane) * 2;
            uint2 b0 = *(const uint2*)wb;
            uint2 b1 = *(const uint2*)(wb + 64);
            mma_bf16(acc0, a, (const unsigned*)&b0);
            mma_bf16(acc1, a, (const unsigned*)&b1);
        }

        // write per-k-half partials: spre2[kh][col 0..63][batch 0..15]
        {
            float* sp = spre2 + kh * 1088;
            int c0 = ntp * 16 + tig * 2;
            sp[(c0)     * 17 + g]     = acc0[0];
            sp[(c0 + 1) * 17 + g]     = acc0[1];
            sp[(c0)     * 17 + g + 8] = acc0[2];
            sp[(c0 + 1) * 17 + g + 8] = acc0[3];
            sp[(c0 + 8) * 17 + g]     = acc1[0];
            sp[(c0 + 9) * 17 + g]     = acc1[1];
            sp[(c0 + 8) * 17 + g + 8] = acc1[2];
            sp[(c0 + 9) * 17 + g + 8] = acc1[3];
        }
        __syncthreads();

        // cell update: thread -> (local batch ub 0..15, unit uu 0..15)
        {
            float pi = spre2[(0  + uu) * 17 + ub] + spre2[1088 + (0  + uu) * 17 + ub] + x0;
            float pf = spre2[(16 + uu) * 17 + ub] + spre2[1088 + (16 + uu) * 17 + ub] + x1;
            float pg = spre2[(32 + uu) * 17 + ub] + spre2[1088 + (32 + uu) * 17 + ub] + x2;
            float po = spre2[(48 + uu) * 17 + ub] + spre2[1088 + (48 + uu) * 17 + ub] + x3;
            float ig = fsigmoid_(pi);
            float fg = fsigmoid_(pf);
            float gg = ftanh_(pg);
            float og = fsigmoid_(po);
            creg = fg * creg + ig * gg;
            float hh = og * ftanh_(creg);
            size_t hidx = (size_t)(bg * 16 + ub) * HID + colg * 16 + uu;
            hout[hidx] = __float2bfloat16(hh);
            if (t == STEPS - 1) g_hf[hidx] = hh;   // fp32 copy for outproj
        }
        domain_barrier(bg, (unsigned)(t + 1));
    }
}

// ---------------- kernel 3: out = h_final @ Wout^T + bout ---------------------
__global__ __launch_bounds__(256, 4) void outproj_kernel(
    const float* __restrict__ Wout, const float* __restrict__ bout,
    float* __restrict__ out) {
    __shared__ float As[2][16][68];
    __shared__ float Bs[2][16][68];

    const int tid = threadIdx.x;
    const int n0 = blockIdx.x * 64;
    const int tn = tid & 15, tb = tid >> 4;
    const float* h = g_hf;   // fp32 final h

    const int arow = tid >> 2, ac4 = tid & 3;

    unsigned long long acc[4][2];
#pragma unroll
    for (int i = 0; i < 4; ++i) { acc[i][0] = 0ull; acc[i][1] = 0ull; }

    float4 pa = make_float4(0.f, 0.f, 0.f, 0.f);
    if (n0 + arow < NCLASS) pa = *(const float4*)(Wout + (size_t)(n0 + arow) * HID + ac4 * 4);
    float4 pbv = *(const float4*)(h + arow * HID + ac4 * 4);

    int cur = 0;
    for (int kt = 0; kt < HID; kt += 16) {
        As[cur][ac4 * 4 + 0][arow] = pa.x;
        As[cur][ac4 * 4 + 1][arow] = pa.y;
        As[cur][ac4 * 4 + 2][arow] = pa.z;
        As[cur][ac4 * 4 + 3][arow] = pa.w;
        Bs[cur][ac4 * 4 + 0][arow] = pbv.x;
        Bs[cur][ac4 * 4 + 1][arow] = pbv.y;
        Bs[cur][ac4 * 4 + 2][arow] = pbv.z;
        Bs[cur][ac4 * 4 + 3][arow] = pbv.w;
        if (kt + 16 < HID) {
            int kn = kt + 16;
            pa = make_float4(0.f, 0.f, 0.f, 0.f);
            if (n0 + arow < NCLASS) pa = *(const float4*)(Wout + (size_t)(n0 + arow) * HID + kn + ac4 * 4);
            pbv = *(const float4*)(h + arow * HID + kn + ac4 * 4);
        }
        __syncthreads();
#pragma unroll
        for (int kk = 0; kk < 16; ++kk) {
            float4 av = *(const float4*)&As[cur][kk][tn * 4];
            float4 bv = *(const float4*)&Bs[cur][kk][tb * 4];
            unsigned long long bp0 = f4lo(bv), bp1 = f4hi(bv);
            float avv[4] = {av.x, av.y, av.z, av.w};
#pragma unroll
            for (int i = 0; i < 4; ++i) {
                unsigned long long ad = pack2(avv[i], avv[i]);
                fma2(acc[i][0], ad, bp0);
                fma2(acc[i][1], ad, bp1);
            }
        }
        cur ^= 1;
    }

#pragma unroll
    for (int i = 0; i < 4; ++i) {
        int n = n0 + tn * 4 + i;
        if (n >= NCLASS) continue;
        float bo = bout[n];
        float2 v0 = unpack2(acc[i][0]);
        float2 v1 = unpack2(acc[i][1]);
        out[(size_t)(tb * 4 + 0) * NCLASS + n] = v0.x + bo;
        out[(size_t)(tb * 4 + 1) * NCLASS + n] = v0.y + bo;
        out[(size_t)(tb * 4 + 2) * NCLASS + n] = v1.x + bo;
        out[(size_t)(tb * 4 + 3) * NCLASS + n] = v1.y + bo;
    }
}

// ---------------- launch --------------------------------------------------------
extern "C" void kernel_launch(void* const* d_in, const int* in_sizes, int n_in,
                              void* d_out, int out_size) {
    const int*   X    = (const int*)d_in[0];
    const float* emb  = (const float*)d_in[1];
    const float* Wi   = (const float*)d_in[2];
    const float* Wh   = (const float*)d_in[3];
    const float* bi   = (const float*)d_in[4];
    const float* bh   = (const float*)d_in[5];
    // d_in[6..9]: layer-2 params — provably unused by the reference output
    const float* Wout = (const float*)d_in[10];
    const float* bout = (const float*)d_in[11];
    float* out = (float*)d_out;

    // allow >48KB dynamic smem (attribute only, not an allocation; idempotent)
    cudaFuncSetAttribute(lstm_bf16_kernel,
                         cudaFuncAttributeMaxDynamicSharedMemorySize, LSTM_SMEM);
    cudaFuncSetAttribute(xw_tf32_kernel,
                         cudaFuncAttributeMaxDynamicSharedMemorySize, SMEM_XW);

    prep_kernel<<<64, 256>>>(bi, bh);
    xw_tf32_kernel<<<dim3(FOURH / 128, (STEPS * BATCH) / 128), 256, SMEM_XW>>>(X, emb, Wi);
    lstm_bf16_kernel<<<128, 256, LSTM_SMEM>>>(Wh);
    outproj_kernel<<<(NCLASS + 63) / 64, 256>>>(Wout, bout, out);
}